// round 1
// baseline (speedup 1.0000x reference)
#include <cuda_runtime.h>

// ---------------------------------------------------------------------------
// Problem constants (from reference)
// ---------------------------------------------------------------------------
#define NU0 20000
#define NI0 15000
#define NU1 4000
#define NI1 3000
#define N0  (NU0 + NI0)   // 35000
#define N1  (NU1 + NI1)   // 7000
#define DEMB 64
#define NLAYERS 3
#define OUTW 256          // D*(L+1)

// ---------------------------------------------------------------------------
// Scratch (static device globals; no runtime allocation)
// ---------------------------------------------------------------------------
__device__ __align__(256) float g_ego0 [N0 * DEMB];
__device__ __align__(256) float g_side0[N0 * DEMB];
__device__ __align__(256) float g_alle0[N0 * OUTW];
__device__ __align__(256) float g_ego1 [N1 * DEMB];
__device__ __align__(256) float g_side1[N1 * DEMB];
__device__ __align__(256) float g_alle1[N1 * OUTW];

// ---------------------------------------------------------------------------
// init: ego = concat(ue, ie); alle[:, 0:64] = ego
// ---------------------------------------------------------------------------
__global__ void init_kernel(const float* __restrict__ ue,
                            const float* __restrict__ ie,
                            float* __restrict__ ego,
                            float* __restrict__ alle,
                            int n_users, int n_nodes) {
    int i = blockIdx.x * blockDim.x + threadIdx.x;
    if (i >= n_nodes * DEMB) return;
    int n = i >> 6;
    int d = i & 63;
    float v = (n < n_users) ? ue[n * DEMB + d] : ie[(n - n_users) * DEMB + d];
    ego[i] = v;
    alle[n * OUTW + d] = v;
}

// ---------------------------------------------------------------------------
// zero (float4)
// ---------------------------------------------------------------------------
__global__ void zero4_kernel(float4* __restrict__ p, int n4) {
    int i = blockIdx.x * blockDim.x + threadIdx.x;
    if (i < n4) p[i] = make_float4(0.f, 0.f, 0.f, 0.f);
}

// ---------------------------------------------------------------------------
// scatter: side[rows[e]] += vals[e] * ego[cols[e]]   (16 threads per edge)
// ---------------------------------------------------------------------------
__global__ void scatter_kernel(const int*   __restrict__ rows,
                               const int*   __restrict__ cols,
                               const float* __restrict__ vals,
                               const float* __restrict__ ego,
                               float*       __restrict__ side,
                               int n_edges) {
    int t = blockIdx.x * blockDim.x + threadIdx.x;
    int e = t >> 4;
    int c = t & 15;
    if (e >= n_edges) return;
    int   col = cols[e];
    int   row = rows[e];
    float v   = vals[e];
    float4 x = ((const float4*)ego)[col * 16 + c];
    float* dst = side + row * DEMB + c * 4;
    atomicAdd(dst + 0, v * x.x);
    atomicAdd(dst + 1, v * x.y);
    atomicAdd(dst + 2, v * x.z);
    atomicAdd(dst + 3, v * x.w);
}

// ---------------------------------------------------------------------------
// layer: per node n:
//   sum_e = lrelu(side[n] @ gcW[l] + gcb[l])
//   bi_e  = lrelu((ego[n]*side[n]) @ biW[l] + bib[l])
//   ego[n] = sum_e + bi_e ;  alle[n, 64*(l+1):] = ego[n]/max(||ego[n]||,1e-12)
// Block: 256 threads = 16 nodes x 16 threads (each thread 4 output dims).
// ---------------------------------------------------------------------------
__global__ __launch_bounds__(256) void layer_kernel(
    const float* __restrict__ gcW, const float* __restrict__ gcb,
    const float* __restrict__ biW, const float* __restrict__ bib,
    const float* __restrict__ side,
    float* __restrict__ ego, float* __restrict__ alle,
    int n_nodes, int layer) {

    __shared__ float4 sGW[64 * 16];   // gcW[l][k][d], float4 over d
    __shared__ float4 sBW[64 * 16];
    __shared__ float  sx [16 * 64];   // side rows
    __shared__ float  sex[16 * 64];   // ego*side rows

    int tid = threadIdx.x;

    const float4* gW4 = (const float4*)(gcW + layer * 64 * 64);
    const float4* bW4 = (const float4*)(biW + layer * 64 * 64);
#pragma unroll
    for (int i = 0; i < 4; i++) {
        sGW[tid + i * 256] = gW4[tid + i * 256];
        sBW[tid + i * 256] = bW4[tid + i * 256];
    }

    int nl = tid >> 4;          // node-in-block 0..15
    int q  = tid & 15;          // dim quad 0..15
    int node = blockIdx.x * 16 + nl;
    bool valid = node < n_nodes;

    float4 x4 = valid ? ((const float4*)side)[node * 16 + q] : make_float4(0,0,0,0);
    float4 e4 = valid ? ((const float4*)ego )[node * 16 + q] : make_float4(0,0,0,0);
    sx [nl * 64 + q * 4 + 0] = x4.x;
    sx [nl * 64 + q * 4 + 1] = x4.y;
    sx [nl * 64 + q * 4 + 2] = x4.z;
    sx [nl * 64 + q * 4 + 3] = x4.w;
    sex[nl * 64 + q * 4 + 0] = e4.x * x4.x;
    sex[nl * 64 + q * 4 + 1] = e4.y * x4.y;
    sex[nl * 64 + q * 4 + 2] = e4.z * x4.z;
    sex[nl * 64 + q * 4 + 3] = e4.w * x4.w;
    __syncthreads();

    float4 a = ((const float4*)(gcb + layer * 64))[q];
    float4 b = ((const float4*)(bib + layer * 64))[q];

#pragma unroll
    for (int k = 0; k < 64; k++) {
        float  xk  = sx [nl * 64 + k];
        float  exk = sex[nl * 64 + k];
        float4 wg  = sGW[k * 16 + q];
        float4 wb  = sBW[k * 16 + q];
        a.x += xk * wg.x;  a.y += xk * wg.y;  a.z += xk * wg.z;  a.w += xk * wg.w;
        b.x += exk * wb.x; b.y += exk * wb.y; b.z += exk * wb.z; b.w += exk * wb.w;
    }

    // leaky relu (slope 0.01) then sum
    a.x = a.x > 0.f ? a.x : 0.01f * a.x;
    a.y = a.y > 0.f ? a.y : 0.01f * a.y;
    a.z = a.z > 0.f ? a.z : 0.01f * a.z;
    a.w = a.w > 0.f ? a.w : 0.01f * a.w;
    b.x = b.x > 0.f ? b.x : 0.01f * b.x;
    b.y = b.y > 0.f ? b.y : 0.01f * b.y;
    b.z = b.z > 0.f ? b.z : 0.01f * b.z;
    b.w = b.w > 0.f ? b.w : 0.01f * b.w;

    float4 eg;
    eg.x = a.x + b.x; eg.y = a.y + b.y; eg.z = a.z + b.z; eg.w = a.w + b.w;

    float ss = eg.x * eg.x + eg.y * eg.y + eg.z * eg.z + eg.w * eg.w;
#pragma unroll
    for (int off = 8; off > 0; off >>= 1)
        ss += __shfl_xor_sync(0xffffffffu, ss, off);   // reduce within 16-lane group

    float r = 1.0f / fmaxf(sqrtf(ss), 1e-12f);

    if (valid) {
        ((float4*)ego)[node * 16 + q] = eg;
        float4 nrm = make_float4(eg.x * r, eg.y * r, eg.z * r, eg.w * r);
        ((float4*)(alle + node * OUTW + (layer + 1) * 64))[q] = nrm;
    }
}

// ---------------------------------------------------------------------------
// Dense GEMM + residual: out[M,256] = base[M,256] + A[M,K] @ B[K,256]
// Classic smem-tiled fp32 SGEMM: BM=128 BN=128 BK=8, 256 threads, 8x8/thread.
// ---------------------------------------------------------------------------
#define BM 128
#define BN 128
#define BK 8
#define TM 8
#define TN 8

__global__ __launch_bounds__(256) void gemm_res_kernel(
    const float* __restrict__ A,     // [M, K]
    const float* __restrict__ B,     // [K, 256]
    const float* __restrict__ base,  // [M, 256]
    float*       __restrict__ out,   // [M, 256]
    int M, int K) {

    __shared__ float As[BK][BM];     // transposed A tile
    __shared__ float Bs[BK][BN];

    int tid = threadIdx.x;
    int blockRow = blockIdx.x * BM;
    int blockCol = blockIdx.y * BN;

    int innerRowA = tid >> 1;           // 0..127
    int innerColA = (tid & 1) * 4;      // 0 or 4
    int innerRowB = tid >> 5;           // 0..7
    int innerColB = (tid & 31) * 4;     // 0..124

    int tRow = (tid >> 4) * TM;         // 0..120
    int tCol = (tid & 15) * TN;         // 0..120

    float acc[TM][TN];
#pragma unroll
    for (int i = 0; i < TM; i++)
#pragma unroll
        for (int j = 0; j < TN; j++) acc[i][j] = 0.f;

    int aRow = blockRow + innerRowA;
    bool aValid = aRow < M;
    const float* Aptr = A + (size_t)aRow * K + innerColA;
    const float* Bptr = B + (size_t)innerRowB * OUTW + blockCol + innerColB;

    for (int k0 = 0; k0 < K; k0 += BK) {
        float4 av = aValid ? *(const float4*)(Aptr + k0)
                           : make_float4(0.f, 0.f, 0.f, 0.f);
        As[innerColA + 0][innerRowA] = av.x;
        As[innerColA + 1][innerRowA] = av.y;
        As[innerColA + 2][innerRowA] = av.z;
        As[innerColA + 3][innerRowA] = av.w;

        float4 bv = *(const float4*)(Bptr + (size_t)k0 * OUTW);
        *(float4*)&Bs[innerRowB][innerColB] = bv;

        __syncthreads();

#pragma unroll
        for (int k = 0; k < BK; k++) {
            float4 m0 = *(const float4*)&As[k][tRow];
            float4 m1 = *(const float4*)&As[k][tRow + 4];
            float4 n0 = *(const float4*)&Bs[k][tCol];
            float4 n1 = *(const float4*)&Bs[k][tCol + 4];
            float regM[TM] = {m0.x, m0.y, m0.z, m0.w, m1.x, m1.y, m1.z, m1.w};
            float regN[TN] = {n0.x, n0.y, n0.z, n0.w, n1.x, n1.y, n1.z, n1.w};
#pragma unroll
            for (int i = 0; i < TM; i++)
#pragma unroll
                for (int j = 0; j < TN; j++)
                    acc[i][j] += regM[i] * regN[j];
        }
        __syncthreads();
    }

#pragma unroll
    for (int i = 0; i < TM; i++) {
        int row = blockRow + tRow + i;
        if (row >= M) continue;
#pragma unroll
        for (int j = 0; j < TN; j += 4) {
            int col = blockCol + tCol + j;
            float4 bs = *(const float4*)(base + (size_t)row * OUTW + col);
            float4 o;
            o.x = acc[i][j + 0] + bs.x;
            o.y = acc[i][j + 1] + bs.y;
            o.z = acc[i][j + 2] + bs.z;
            o.w = acc[i][j + 3] + bs.w;
            *(float4*)(out + (size_t)row * OUTW + col) = o;
        }
    }
}

// ---------------------------------------------------------------------------
// Launch
// ---------------------------------------------------------------------------
extern "C" void kernel_launch(void* const* d_in, const int* in_sizes, int n_in,
                              void* d_out, int out_size) {
    const float* ue0  = (const float*)d_in[0];
    const float* ie0  = (const float*)d_in[1];
    const float* gcW0 = (const float*)d_in[2];
    const float* gcb0 = (const float*)d_in[3];
    const float* biW0 = (const float*)d_in[4];
    const float* bib0 = (const float*)d_in[5];
    const float* ue1  = (const float*)d_in[6];
    const float* ie1  = (const float*)d_in[7];
    const float* gcW1 = (const float*)d_in[8];
    const float* gcb1 = (const float*)d_in[9];
    const float* biW1 = (const float*)d_in[10];
    const float* bib1 = (const float*)d_in[11];
    const float* mapu = (const float*)d_in[12];
    const float* mapi = (const float*)d_in[13];
    const float* vals0 = (const float*)d_in[14];
    const float* vals1 = (const float*)d_in[15];
    const int*   rows0 = (const int*)d_in[16];
    const int*   cols0 = (const int*)d_in[17];
    const int*   rows1 = (const int*)d_in[18];
    const int*   cols1 = (const int*)d_in[19];
    float* out = (float*)d_out;

    int E0 = in_sizes[14];
    int E1 = in_sizes[15];

    float *ego0, *side0, *alle0, *ego1, *side1, *alle1;
    cudaGetSymbolAddress((void**)&ego0,  g_ego0);
    cudaGetSymbolAddress((void**)&side0, g_side0);
    cudaGetSymbolAddress((void**)&alle0, g_alle0);
    cudaGetSymbolAddress((void**)&ego1,  g_ego1);
    cudaGetSymbolAddress((void**)&side1, g_side1);
    cudaGetSymbolAddress((void**)&alle1, g_alle1);

    // init
    init_kernel<<<(N0 * DEMB + 255) / 256, 256>>>(ue0, ie0, ego0, alle0, NU0, N0);
    init_kernel<<<(N1 * DEMB + 255) / 256, 256>>>(ue1, ie1, ego1, alle1, NU1, N1);

    for (int l = 0; l < NLAYERS; l++) {
        // graph 0
        zero4_kernel<<<(N0 * 16 + 255) / 256, 256>>>((float4*)side0, N0 * 16);
        scatter_kernel<<<((long long)E0 * 16 + 255) / 256, 256>>>(
            rows0, cols0, vals0, ego0, side0, E0);
        layer_kernel<<<(N0 + 15) / 16, 256>>>(
            gcW0, gcb0, biW0, bib0, side0, ego0, alle0, N0, l);
        // graph 1
        zero4_kernel<<<(N1 * 16 + 255) / 256, 256>>>((float4*)side1, N1 * 16);
        scatter_kernel<<<((long long)E1 * 16 + 255) / 256, 256>>>(
            rows1, cols1, vals1, ego1, side1, E1);
        layer_kernel<<<(N1 + 15) / 16, 256>>>(
            gcW1, gcb1, biW1, bib1, side1, ego1, alle1, N1, l);
    }

    // user_embd = ug0 + mapu @ ug1
    {
        dim3 grid((NU0 + BM - 1) / BM, OUTW / BN);
        gemm_res_kernel<<<grid, 256>>>(mapu, alle1, alle0, out, NU0, NU1);
    }
    // item_embd = ig0 + mapi @ ig1
    {
        dim3 grid((NI0 + BM - 1) / BM, OUTW / BN);
        gemm_res_kernel<<<grid, 256>>>(mapi, alle1 + (size_t)NU1 * OUTW,
                                       alle0 + (size_t)NU0 * OUTW,
                                       out + (size_t)NU0 * OUTW, NI0, NI1);
    }
}

// round 3
// speedup vs baseline: 1.3211x; 1.3211x over previous
#include <cuda_runtime.h>
#include <cuda_bf16.h>
#include <mma.h>
#include <cstdint>

using namespace nvcuda;

// ---------------------------------------------------------------------------
// Problem constants
// ---------------------------------------------------------------------------
#define NU0 20000
#define NI0 15000
#define NU1 4000
#define NI1 3000
#define N0  (NU0 + NI0)   // 35000
#define N1  (NU1 + NI1)   // 7000
#define DEMB 64
#define NLAYERS 3
#define OUTW 256          // D*(L+1)

#define KPAD_U 4032       // ceil(4000/32)*32
#define KPAD_I 3008       // ceil(3000/32)*32

#define BLOCKS_U 157      // ceil(20000/128)
#define BLOCKS_I 118      // ceil(15000/128)

// ---------------------------------------------------------------------------
// Scratch (static device globals)
// ---------------------------------------------------------------------------
__device__ __align__(256) float g_ego0 [N0 * DEMB];
__device__ __align__(256) float g_side0[N0 * DEMB];
__device__ __align__(256) float g_alle0[N0 * OUTW];
__device__ __align__(256) float g_ego1 [N1 * DEMB];
__device__ __align__(256) float g_side1[N1 * DEMB];
__device__ __align__(256) float g_alle1[N1 * OUTW];

// Pre-split / pre-transposed B for tf32 GEMM: B*(n, k) K-major, zero-padded.
// Values are exact tf32 (low 13 mantissa bits zero), stored as fp32.
__device__ __align__(256) float g_Bh_u[256 * KPAD_U];
__device__ __align__(256) float g_Bl_u[256 * KPAD_U];
__device__ __align__(256) float g_Bh_i[256 * KPAD_I];
__device__ __align__(256) float g_Bl_i[256 * KPAD_I];

// ---------------------------------------------------------------------------
// helpers
// ---------------------------------------------------------------------------
__device__ __forceinline__ float to_tf32(float x) {
    float r;
    asm("cvt.rna.tf32.f32 %0, %1;" : "=f"(r) : "f"(x));
    return r;
}

// ---------------------------------------------------------------------------
// init: ego = concat(ue, ie); alle[:, 0:64] = ego
// ---------------------------------------------------------------------------
__global__ void init_kernel(const float* __restrict__ ue,
                            const float* __restrict__ ie,
                            float* __restrict__ ego,
                            float* __restrict__ alle,
                            int n_users, int n_nodes) {
    int i = blockIdx.x * blockDim.x + threadIdx.x;
    if (i >= n_nodes * DEMB) return;
    int n = i >> 6;
    int d = i & 63;
    float v = (n < n_users) ? ue[n * DEMB + d] : ie[(n - n_users) * DEMB + d];
    ego[i] = v;
    alle[n * OUTW + d] = v;
}

__global__ void zero4_kernel(float4* __restrict__ p, int n4) {
    int i = blockIdx.x * blockDim.x + threadIdx.x;
    if (i < n4) p[i] = make_float4(0.f, 0.f, 0.f, 0.f);
}

// ---------------------------------------------------------------------------
// scatter: side[rows[e]] += vals[e] * ego[cols[e]]   (16 threads per edge)
// ---------------------------------------------------------------------------
__global__ void scatter_kernel(const int*   __restrict__ rows,
                               const int*   __restrict__ cols,
                               const float* __restrict__ vals,
                               const float* __restrict__ ego,
                               float*       __restrict__ side,
                               int n_edges) {
    int t = blockIdx.x * blockDim.x + threadIdx.x;
    int e = t >> 4;
    int c = t & 15;
    if (e >= n_edges) return;
    int   col = cols[e];
    int   row = rows[e];
    float v   = vals[e];
    float4 x = ((const float4*)ego)[col * 16 + c];
    float* dst = side + row * DEMB + c * 4;
    atomicAdd(dst + 0, v * x.x);
    atomicAdd(dst + 1, v * x.y);
    atomicAdd(dst + 2, v * x.z);
    atomicAdd(dst + 3, v * x.w);
}

// ---------------------------------------------------------------------------
// layer kernel (unchanged; passed round 1)
// ---------------------------------------------------------------------------
__global__ __launch_bounds__(256) void layer_kernel(
    const float* __restrict__ gcW, const float* __restrict__ gcb,
    const float* __restrict__ biW, const float* __restrict__ bib,
    const float* __restrict__ side,
    float* __restrict__ ego, float* __restrict__ alle,
    int n_nodes, int layer) {

    __shared__ float4 sGW[64 * 16];
    __shared__ float4 sBW[64 * 16];
    __shared__ float  sx [16 * 64];
    __shared__ float  sex[16 * 64];

    int tid = threadIdx.x;

    const float4* gW4 = (const float4*)(gcW + layer * 64 * 64);
    const float4* bW4 = (const float4*)(biW + layer * 64 * 64);
#pragma unroll
    for (int i = 0; i < 4; i++) {
        sGW[tid + i * 256] = gW4[tid + i * 256];
        sBW[tid + i * 256] = bW4[tid + i * 256];
    }

    int nl = tid >> 4;
    int q  = tid & 15;
    int node = blockIdx.x * 16 + nl;
    bool valid = node < n_nodes;

    float4 x4 = valid ? ((const float4*)side)[node * 16 + q] : make_float4(0,0,0,0);
    float4 e4 = valid ? ((const float4*)ego )[node * 16 + q] : make_float4(0,0,0,0);
    sx [nl * 64 + q * 4 + 0] = x4.x;
    sx [nl * 64 + q * 4 + 1] = x4.y;
    sx [nl * 64 + q * 4 + 2] = x4.z;
    sx [nl * 64 + q * 4 + 3] = x4.w;
    sex[nl * 64 + q * 4 + 0] = e4.x * x4.x;
    sex[nl * 64 + q * 4 + 1] = e4.y * x4.y;
    sex[nl * 64 + q * 4 + 2] = e4.z * x4.z;
    sex[nl * 64 + q * 4 + 3] = e4.w * x4.w;
    __syncthreads();

    float4 a = ((const float4*)(gcb + layer * 64))[q];
    float4 b = ((const float4*)(bib + layer * 64))[q];

#pragma unroll
    for (int k = 0; k < 64; k++) {
        float  xk  = sx [nl * 64 + k];
        float  exk = sex[nl * 64 + k];
        float4 wg  = sGW[k * 16 + q];
        float4 wb  = sBW[k * 16 + q];
        a.x += xk * wg.x;  a.y += xk * wg.y;  a.z += xk * wg.z;  a.w += xk * wg.w;
        b.x += exk * wb.x; b.y += exk * wb.y; b.z += exk * wb.z; b.w += exk * wb.w;
    }

    a.x = a.x > 0.f ? a.x : 0.01f * a.x;
    a.y = a.y > 0.f ? a.y : 0.01f * a.y;
    a.z = a.z > 0.f ? a.z : 0.01f * a.z;
    a.w = a.w > 0.f ? a.w : 0.01f * a.w;
    b.x = b.x > 0.f ? b.x : 0.01f * b.x;
    b.y = b.y > 0.f ? b.y : 0.01f * b.y;
    b.z = b.z > 0.f ? b.z : 0.01f * b.z;
    b.w = b.w > 0.f ? b.w : 0.01f * b.w;

    float4 eg;
    eg.x = a.x + b.x; eg.y = a.y + b.y; eg.z = a.z + b.z; eg.w = a.w + b.w;

    float ss = eg.x * eg.x + eg.y * eg.y + eg.z * eg.z + eg.w * eg.w;
#pragma unroll
    for (int off = 8; off > 0; off >>= 1)
        ss += __shfl_xor_sync(0xffffffffu, ss, off);

    float r = 1.0f / fmaxf(sqrtf(ss), 1e-12f);

    if (valid) {
        ((float4*)ego)[node * 16 + q] = eg;
        float4 nrm = make_float4(eg.x * r, eg.y * r, eg.z * r, eg.w * r);
        ((float4*)(alle + node * OUTW + (layer + 1) * 64))[q] = nrm;
    }
}

// ---------------------------------------------------------------------------
// convertB: Bh/Bl[n][k] = tf32 split of B[k][n] (K-major, zero-padded)
// ---------------------------------------------------------------------------
__global__ void convertB_kernel(const float* __restrict__ B, int K, int Kpad,
                                float* __restrict__ hi,
                                float* __restrict__ lo) {
    int idx = blockIdx.x * blockDim.x + threadIdx.x;
    if (idx >= 256 * Kpad) return;
    int n = idx & 255;
    int k = idx >> 8;
    float v = (k < K) ? B[(size_t)k * 256 + n] : 0.f;
    float h = to_tf32(v);
    float l = to_tf32(v - h);
    hi[(size_t)n * Kpad + k] = h;
    lo[(size_t)n * Kpad + k] = l;
}

// ---------------------------------------------------------------------------
// tf32 WMMA GEMM + residual, both GEMMs in one launch.
//   out[M,256] = base[M,256] + A[M,K] @ B[K,256]
// B pre-split (Bh + Bl exactly reproduces fp32 B); A converted tf32 on the fly.
// Block tile 128x128, BK=32, 8 warps each 32x64, 2 CTAs/SM.
// ---------------------------------------------------------------------------
#define LDS_A 40   // smem leading dim (elements) for all three tiles

__global__ __launch_bounds__(256, 2) void wmma_gemm_kernel(
    const float* __restrict__ Au, const float* __restrict__ Ai,
    const float* __restrict__ Bhu, const float* __restrict__ Blu,
    const float* __restrict__ Bhi, const float* __restrict__ Bli,
    const float* __restrict__ baseU, const float* __restrict__ baseI,
    float* __restrict__ outU, float* __restrict__ outI) {

    extern __shared__ float sm[];
    float* As = sm;                    // [128][LDS_A]
    float* Bh = sm + 128 * LDS_A;      // [128][LDS_A]
    float* Bl = Bh + 128 * LDS_A;      // [128][LDS_A]

    bool isU = blockIdx.x < BLOCKS_U;
    const float* A    = isU ? Au    : Ai;
    const float* BHg  = isU ? Bhu   : Bhi;
    const float* BLg  = isU ? Blu   : Bli;
    const float* base = isU ? baseU : baseI;
    float*       out  = isU ? outU  : outI;
    int M    = isU ? NU0 : NI0;
    int K    = isU ? NU1 : NI1;
    int Kpad = isU ? KPAD_U : KPAD_I;
    int blockRow = (isU ? blockIdx.x : blockIdx.x - BLOCKS_U) * 128;
    int blockCol = blockIdx.y * 128;

    int tid = threadIdx.x;
    int wid = tid >> 5;
    int lane = tid & 31;
    int wm = (wid >> 1) * 32;   // warp row offset within tile
    int wn = (wid & 1) * 64;    // warp col offset within tile

    bool interior = (blockRow + 128 <= M);

    wmma::fragment<wmma::accumulator, 16, 16, 8, float> c[2][4];
    if (interior) {
#pragma unroll
        for (int i = 0; i < 2; i++)
#pragma unroll
            for (int j = 0; j < 4; j++)
                wmma::load_matrix_sync(
                    c[i][j],
                    base + (size_t)(blockRow + wm + i * 16) * OUTW
                         + blockCol + wn + j * 16,
                    OUTW, wmma::mem_row_major);
    } else {
#pragma unroll
        for (int i = 0; i < 2; i++)
#pragma unroll
            for (int j = 0; j < 4; j++)
                wmma::fill_fragment(c[i][j], 0.f);
    }

    for (int kc = 0; kc < Kpad; kc += 32) {
        __syncthreads();   // previous iteration's fragment reads done

        // ---- A tile [128 x 32] fp32 -> tf32(rna) in smem ----
#pragma unroll
        for (int i = 0; i < 4; i++) {
            int idx = tid + i * 256;        // 0..1023
            int r = idx >> 3;               // 0..127
            int q = idx & 7;                // 0..7
            int grow = blockRow + r;
            int gcol = kc + q * 4;
            float4 v = make_float4(0.f, 0.f, 0.f, 0.f);
            if (grow < M && gcol < K)
                v = *(const float4*)(A + (size_t)grow * K + gcol);
            float* d = As + r * LDS_A + q * 4;
            d[0] = to_tf32(v.x);
            d[1] = to_tf32(v.y);
            d[2] = to_tf32(v.z);
            d[3] = to_tf32(v.w);
        }

        // ---- B tiles [128n x 32k] (already tf32 values) ----
#pragma unroll
        for (int i = 0; i < 4; i++) {
            int idx = tid + i * 256;
            int n = idx >> 3;
            int q = idx & 7;
            size_t goff = (size_t)(blockCol + n) * Kpad + kc + q * 4;
            float4 vh = *(const float4*)(BHg + goff);
            float4 vl = *(const float4*)(BLg + goff);
            *(float4*)(Bh + n * LDS_A + q * 4) = vh;
            *(float4*)(Bl + n * LDS_A + q * 4) = vl;
        }
        __syncthreads();

        // ---- MMA: 4 k-frags x (2m x 4n) x 2 passes ----
#pragma unroll
        for (int kk = 0; kk < 4; kk++) {
            wmma::fragment<wmma::matrix_a, 16, 16, 8,
                           wmma::precision::tf32, wmma::row_major> a0, a1;
            wmma::load_matrix_sync(a0, As + (wm)      * LDS_A + kk * 8, LDS_A);
            wmma::load_matrix_sync(a1, As + (wm + 16) * LDS_A + kk * 8, LDS_A);
#pragma unroll
            for (int j = 0; j < 4; j++) {
                wmma::fragment<wmma::matrix_b, 16, 16, 8,
                               wmma::precision::tf32, wmma::col_major> bh, bl;
                wmma::load_matrix_sync(bh, Bh + (wn + j * 16) * LDS_A + kk * 8, LDS_A);
                wmma::load_matrix_sync(bl, Bl + (wn + j * 16) * LDS_A + kk * 8, LDS_A);
                wmma::mma_sync(c[0][j], a0, bh, c[0][j]);
                wmma::mma_sync(c[1][j], a1, bh, c[1][j]);
                wmma::mma_sync(c[0][j], a0, bl, c[0][j]);
                wmma::mma_sync(c[1][j], a1, bl, c[1][j]);
            }
        }
    }

    // ---- epilogue ----
    if (interior) {
#pragma unroll
        for (int i = 0; i < 2; i++)
#pragma unroll
            for (int j = 0; j < 4; j++)
                wmma::store_matrix_sync(
                    out + (size_t)(blockRow + wm + i * 16) * OUTW
                        + blockCol + wn + j * 16,
                    c[i][j], OUTW, wmma::mem_row_major);
    } else {
        // boundary block: stage fragments through smem, guarded add+store
        __syncthreads();
        float* stg = sm + wid * 256;   // per-warp 16x16 staging (reuses As)
#pragma unroll
        for (int i = 0; i < 2; i++)
#pragma unroll
            for (int j = 0; j < 4; j++) {
                wmma::store_matrix_sync(stg, c[i][j], 16, wmma::mem_row_major);
                __syncwarp();
#pragma unroll
                for (int e = 0; e < 8; e++) {
                    int el = lane + e * 32;
                    int r  = el >> 4;
                    int cc = el & 15;
                    int grow = blockRow + wm + i * 16 + r;
                    if (grow < M) {
                        int gc = blockCol + wn + j * 16 + cc;
                        out[(size_t)grow * OUTW + gc] =
                            stg[el] + base[(size_t)grow * OUTW + gc];
                    }
                }
                __syncwarp();
            }
    }
}

// ---------------------------------------------------------------------------
// Launch
// ---------------------------------------------------------------------------
extern "C" void kernel_launch(void* const* d_in, const int* in_sizes, int n_in,
                              void* d_out, int out_size) {
    const float* ue0  = (const float*)d_in[0];
    const float* ie0  = (const float*)d_in[1];
    const float* gcW0 = (const float*)d_in[2];
    const float* gcb0 = (const float*)d_in[3];
    const float* biW0 = (const float*)d_in[4];
    const float* bib0 = (const float*)d_in[5];
    const float* ue1  = (const float*)d_in[6];
    const float* ie1  = (const float*)d_in[7];
    const float* gcW1 = (const float*)d_in[8];
    const float* gcb1 = (const float*)d_in[9];
    const float* biW1 = (const float*)d_in[10];
    const float* bib1 = (const float*)d_in[11];
    const float* mapu = (const float*)d_in[12];
    const float* mapi = (const float*)d_in[13];
    const float* vals0 = (const float*)d_in[14];
    const float* vals1 = (const float*)d_in[15];
    const int*   rows0 = (const int*)d_in[16];
    const int*   cols0 = (const int*)d_in[17];
    const int*   rows1 = (const int*)d_in[18];
    const int*   cols1 = (const int*)d_in[19];
    float* out = (float*)d_out;

    int E0 = in_sizes[14];
    int E1 = in_sizes[15];

    float *ego0, *side0, *alle0, *ego1, *side1, *alle1;
    cudaGetSymbolAddress((void**)&ego0,  g_ego0);
    cudaGetSymbolAddress((void**)&side0, g_side0);
    cudaGetSymbolAddress((void**)&alle0, g_alle0);
    cudaGetSymbolAddress((void**)&ego1,  g_ego1);
    cudaGetSymbolAddress((void**)&side1, g_side1);
    cudaGetSymbolAddress((void**)&alle1, g_alle1);

    float *bhu, *blu, *bhi, *bli;
    cudaGetSymbolAddress((void**)&bhu, g_Bh_u);
    cudaGetSymbolAddress((void**)&blu, g_Bl_u);
    cudaGetSymbolAddress((void**)&bhi, g_Bh_i);
    cudaGetSymbolAddress((void**)&bli, g_Bl_i);

    const int gemm_smem = 3 * 128 * LDS_A * sizeof(float);   // 61440
    cudaFuncSetAttribute(wmma_gemm_kernel,
                         cudaFuncAttributeMaxDynamicSharedMemorySize,
                         gemm_smem);

    // init
    init_kernel<<<(N0 * DEMB + 255) / 256, 256>>>(ue0, ie0, ego0, alle0, NU0, N0);
    init_kernel<<<(N1 * DEMB + 255) / 256, 256>>>(ue1, ie1, ego1, alle1, NU1, N1);

    for (int l = 0; l < NLAYERS; l++) {
        zero4_kernel<<<(N0 * 16 + 255) / 256, 256>>>((float4*)side0, N0 * 16);
        scatter_kernel<<<((long long)E0 * 16 + 255) / 256, 256>>>(
            rows0, cols0, vals0, ego0, side0, E0);
        layer_kernel<<<(N0 + 15) / 16, 256>>>(
            gcW0, gcb0, biW0, bib0, side0, ego0, alle0, N0, l);

        zero4_kernel<<<(N1 * 16 + 255) / 256, 256>>>((float4*)side1, N1 * 16);
        scatter_kernel<<<((long long)E1 * 16 + 255) / 256, 256>>>(
            rows1, cols1, vals1, ego1, side1, E1);
        layer_kernel<<<(N1 + 15) / 16, 256>>>(
            gcW1, gcb1, biW1, bib1, side1, ego1, alle1, N1, l);
    }

    // pre-split/transpose B operands
    convertB_kernel<<<KPAD_U, 256>>>(alle1, NU1, KPAD_U, bhu, blu);
    convertB_kernel<<<KPAD_I, 256>>>(alle1 + (size_t)NU1 * OUTW, NI1, KPAD_I,
                                     bhi, bli);

    // both residual GEMMs in a single launch
    dim3 grid(BLOCKS_U + BLOCKS_I, 2);
    wmma_gemm_kernel<<<grid, 256, gemm_smem>>>(
        mapu, mapi, bhu, blu, bhi, bli,
        alle0, alle0 + (size_t)NU0 * OUTW,
        out, out + (size_t)NU0 * OUTW);
}

// round 4
// speedup vs baseline: 3.8493x; 2.9138x over previous
#include <cuda_runtime.h>
#include <cuda_fp16.h>
#include <mma.h>
#include <cstdint>

using namespace nvcuda;

// ---------------------------------------------------------------------------
// Problem constants
// ---------------------------------------------------------------------------
#define NU0 20000
#define NI0 15000
#define NU1 4000
#define NI1 3000
#define N0  (NU0 + NI0)   // 35000
#define N1  (NU1 + NI1)   // 7000
#define DEMB 64
#define NLAYERS 3
#define OUTW 256          // D*(L+1)

#define KPAD_U 4032       // multiple of 32 (and 64)
#define KPAD_I 3008

#define BLOCKS_U 157      // ceil(20000/128)
#define BLOCKS_I 118      // ceil(15000/128)

// ---------------------------------------------------------------------------
// Scratch (static device globals)
// ---------------------------------------------------------------------------
__device__ __align__(256) float g_ego0 [N0 * DEMB];
__device__ __align__(256) float g_side0[N0 * DEMB];
__device__ __align__(256) float g_alle0[N0 * OUTW];
__device__ __align__(256) float g_ego1 [N1 * DEMB];
__device__ __align__(256) float g_side1[N1 * DEMB];
__device__ __align__(256) float g_alle1[N1 * OUTW];

// Pre-split / pre-transposed B (fp16 hi/lo), K-major [256][Kpad], zero-padded.
__device__ __align__(256) __half g_Bh_u[256 * KPAD_U];
__device__ __align__(256) __half g_Bl_u[256 * KPAD_U];
__device__ __align__(256) __half g_Bh_i[256 * KPAD_I];
__device__ __align__(256) __half g_Bl_i[256 * KPAD_I];

// ---------------------------------------------------------------------------
// init: ego = concat(ue, ie); alle[:, 0:64] = ego
// ---------------------------------------------------------------------------
__global__ void init_kernel(const float* __restrict__ ue,
                            const float* __restrict__ ie,
                            float* __restrict__ ego,
                            float* __restrict__ alle,
                            int n_users, int n_nodes) {
    int i = blockIdx.x * blockDim.x + threadIdx.x;
    if (i >= n_nodes * DEMB) return;
    int n = i >> 6;
    int d = i & 63;
    float v = (n < n_users) ? ue[n * DEMB + d] : ie[(n - n_users) * DEMB + d];
    ego[i] = v;
    alle[n * OUTW + d] = v;
}

__global__ void zero4_kernel(float4* __restrict__ p, int n4) {
    int i = blockIdx.x * blockDim.x + threadIdx.x;
    if (i < n4) p[i] = make_float4(0.f, 0.f, 0.f, 0.f);
}

// ---------------------------------------------------------------------------
// scatter: side[rows[e]] += vals[e] * ego[cols[e]]
// 16 threads per edge, one red.global.add.v4.f32 per thread (sm_90+ vector red)
// ---------------------------------------------------------------------------
__global__ void scatter_kernel(const int*   __restrict__ rows,
                               const int*   __restrict__ cols,
                               const float* __restrict__ vals,
                               const float* __restrict__ ego,
                               float*       __restrict__ side,
                               int n_edges) {
    int t = blockIdx.x * blockDim.x + threadIdx.x;
    int e = t >> 4;
    int c = t & 15;
    if (e >= n_edges) return;
    int   col = cols[e];
    int   row = rows[e];
    float v   = vals[e];
    float4 x = ((const float4*)ego)[col * 16 + c];
    float4 y = make_float4(v * x.x, v * x.y, v * x.z, v * x.w);
    float* dst = side + row * DEMB + c * 4;
    asm volatile("red.global.add.v4.f32 [%0], {%1, %2, %3, %4};"
                 :: "l"(dst), "f"(y.x), "f"(y.y), "f"(y.z), "f"(y.w)
                 : "memory");
}

// ---------------------------------------------------------------------------
// layer kernel (unchanged; verified correct, ~noise-level cost)
// ---------------------------------------------------------------------------
__global__ __launch_bounds__(256) void layer_kernel(
    const float* __restrict__ gcW, const float* __restrict__ gcb,
    const float* __restrict__ biW, const float* __restrict__ bib,
    const float* __restrict__ side,
    float* __restrict__ ego, float* __restrict__ alle,
    int n_nodes, int layer) {

    __shared__ float4 sGW[64 * 16];
    __shared__ float4 sBW[64 * 16];
    __shared__ float  sx [16 * 64];
    __shared__ float  sex[16 * 64];

    int tid = threadIdx.x;

    const float4* gW4 = (const float4*)(gcW + layer * 64 * 64);
    const float4* bW4 = (const float4*)(biW + layer * 64 * 64);
#pragma unroll
    for (int i = 0; i < 4; i++) {
        sGW[tid + i * 256] = gW4[tid + i * 256];
        sBW[tid + i * 256] = bW4[tid + i * 256];
    }

    int nl = tid >> 4;
    int q  = tid & 15;
    int node = blockIdx.x * 16 + nl;
    bool valid = node < n_nodes;

    float4 x4 = valid ? ((const float4*)side)[node * 16 + q] : make_float4(0,0,0,0);
    float4 e4 = valid ? ((const float4*)ego )[node * 16 + q] : make_float4(0,0,0,0);
    sx [nl * 64 + q * 4 + 0] = x4.x;
    sx [nl * 64 + q * 4 + 1] = x4.y;
    sx [nl * 64 + q * 4 + 2] = x4.z;
    sx [nl * 64 + q * 4 + 3] = x4.w;
    sex[nl * 64 + q * 4 + 0] = e4.x * x4.x;
    sex[nl * 64 + q * 4 + 1] = e4.y * x4.y;
    sex[nl * 64 + q * 4 + 2] = e4.z * x4.z;
    sex[nl * 64 + q * 4 + 3] = e4.w * x4.w;
    __syncthreads();

    float4 a = ((const float4*)(gcb + layer * 64))[q];
    float4 b = ((const float4*)(bib + layer * 64))[q];

#pragma unroll
    for (int k = 0; k < 64; k++) {
        float  xk  = sx [nl * 64 + k];
        float  exk = sex[nl * 64 + k];
        float4 wg  = sGW[k * 16 + q];
        float4 wb  = sBW[k * 16 + q];
        a.x += xk * wg.x;  a.y += xk * wg.y;  a.z += xk * wg.z;  a.w += xk * wg.w;
        b.x += exk * wb.x; b.y += exk * wb.y; b.z += exk * wb.z; b.w += exk * wb.w;
    }

    a.x = a.x > 0.f ? a.x : 0.01f * a.x;
    a.y = a.y > 0.f ? a.y : 0.01f * a.y;
    a.z = a.z > 0.f ? a.z : 0.01f * a.z;
    a.w = a.w > 0.f ? a.w : 0.01f * a.w;
    b.x = b.x > 0.f ? b.x : 0.01f * b.x;
    b.y = b.y > 0.f ? b.y : 0.01f * b.y;
    b.z = b.z > 0.f ? b.z : 0.01f * b.z;
    b.w = b.w > 0.f ? b.w : 0.01f * b.w;

    float4 eg;
    eg.x = a.x + b.x; eg.y = a.y + b.y; eg.z = a.z + b.z; eg.w = a.w + b.w;

    float ss = eg.x * eg.x + eg.y * eg.y + eg.z * eg.z + eg.w * eg.w;
#pragma unroll
    for (int off = 8; off > 0; off >>= 1)
        ss += __shfl_xor_sync(0xffffffffu, ss, off);

    float r = 1.0f / fmaxf(sqrtf(ss), 1e-12f);

    if (valid) {
        ((float4*)ego)[node * 16 + q] = eg;
        float4 nrm = make_float4(eg.x * r, eg.y * r, eg.z * r, eg.w * r);
        ((float4*)(alle + node * OUTW + (layer + 1) * 64))[q] = nrm;
    }
}

// ---------------------------------------------------------------------------
// convertB: Bh/Bl[n][k] = fp16 split of B[k][n] (K-major, zero-padded)
// ---------------------------------------------------------------------------
__global__ void convertB_kernel(const float* __restrict__ B, int K, int Kpad,
                                __half* __restrict__ hi,
                                __half* __restrict__ lo) {
    int idx = blockIdx.x * blockDim.x + threadIdx.x;
    if (idx >= 256 * Kpad) return;
    int n = idx & 255;
    int k = idx >> 8;
    float v = (k < K) ? B[(size_t)k * 256 + n] : 0.f;
    __half h = __float2half_rn(v);
    __half l = __float2half_rn(v - __half2float(h));
    hi[(size_t)n * Kpad + k] = h;
    lo[(size_t)n * Kpad + k] = l;
}

// ---------------------------------------------------------------------------
// fp16 WMMA GEMM + residual, cp.async double-buffered.
//   out[M,256] = base[M,256] + A[M,K] @ (Bh + Bl)[K,256]
// A: fp32 -> fp16 on the fly (register prefetch). B: pre-split fp16 hi/lo.
// Block tile 128x128, BK=32, 8 warps each 32x64, 2 CTAs/SM.
// ---------------------------------------------------------------------------
#define LDH 40            // smem leading dim in halves (80B rows, 16B multiple)
#define TILE_H (128 * LDH)   // halves per tile buffer

__device__ __forceinline__ void cp_async16(uint32_t saddr, const void* gptr) {
    asm volatile("cp.async.cg.shared.global [%0], [%1], 16;"
                 :: "r"(saddr), "l"(gptr));
}
__device__ __forceinline__ void cp_commit() {
    asm volatile("cp.async.commit_group;");
}
__device__ __forceinline__ void cp_wait_all() {
    asm volatile("cp.async.wait_group 0;" ::: "memory");
}

__global__ __launch_bounds__(256, 2) void wmma_gemm_kernel(
    const float* __restrict__ Au, const float* __restrict__ Ai,
    const __half* __restrict__ Bhu, const __half* __restrict__ Blu,
    const __half* __restrict__ Bhi, const __half* __restrict__ Bli,
    const float* __restrict__ baseU, const float* __restrict__ baseI,
    float* __restrict__ outU, float* __restrict__ outI) {

    extern __shared__ __half sm[];
    __half* As = sm;                      // [2][128][LDH]
    __half* Bh = sm + 2 * TILE_H;         // [2][128][LDH]
    __half* Bl = sm + 4 * TILE_H;         // [2][128][LDH]

    bool isU = blockIdx.x < BLOCKS_U;
    const float*  A    = isU ? Au    : Ai;
    const __half* BHg  = isU ? Bhu   : Bhi;
    const __half* BLg  = isU ? Blu   : Bli;
    const float*  base = isU ? baseU : baseI;
    float*        out  = isU ? outU  : outI;
    int M    = isU ? NU0 : NI0;
    int K    = isU ? NU1 : NI1;
    int Kpad = isU ? KPAD_U : KPAD_I;
    int blockRow = (isU ? blockIdx.x : blockIdx.x - BLOCKS_U) * 128;
    int blockCol = blockIdx.y * 128;

    int tid  = threadIdx.x;
    int wid  = tid >> 5;
    int lane = tid & 31;
    int wm = (wid >> 1) * 32;
    int wn = (wid & 1) * 64;

    bool interior = (blockRow + 128 <= M);

    // A-load mapping: 4 float4 per thread per chunk
    int ar = tid >> 3;              // row 0..31 (x4 via i)
    int aq = tid & 7;               // float4 within 32-col row
    // B-load mapping: 2 x 16B units per tile per thread
    int bn = tid >> 2;              // row 0..63 (x2 via i)
    int bu = tid & 3;               // 16B unit within 64B row

    uint32_t sAs = (uint32_t)__cvta_generic_to_shared(As);
    uint32_t sBh = (uint32_t)__cvta_generic_to_shared(Bh);
    uint32_t sBl = (uint32_t)__cvta_generic_to_shared(Bl);

    wmma::fragment<wmma::accumulator, 16, 16, 16, float> c[2][4];
    if (interior) {
#pragma unroll
        for (int i = 0; i < 2; i++)
#pragma unroll
            for (int j = 0; j < 4; j++)
                wmma::load_matrix_sync(
                    c[i][j],
                    base + (size_t)(blockRow + wm + i * 16) * OUTW
                         + blockCol + wn + j * 16,
                    OUTW, wmma::mem_row_major);
    } else {
#pragma unroll
        for (int i = 0; i < 2; i++)
#pragma unroll
            for (int j = 0; j < 4; j++)
                wmma::fill_fragment(c[i][j], 0.f);
    }

    int nCh = Kpad >> 5;
    float4 aReg[4];

    // prologue: B chunk 0 -> buf 0; A chunk 0 -> regs
    {
#pragma unroll
        for (int i = 0; i < 2; i++) {
            int n = bn + i * 64;
            const __half* srcH = BHg + (size_t)(blockCol + n) * Kpad + bu * 8;
            const __half* srcL = BLg + (size_t)(blockCol + n) * Kpad + bu * 8;
            uint32_t off = (uint32_t)(n * LDH + bu * 8) * 2;
            cp_async16(sBh + off, srcH);
            cp_async16(sBl + off, srcL);
        }
        cp_commit();
#pragma unroll
        for (int i = 0; i < 4; i++) {
            int r = ar + i * 32;
            int grow = blockRow + r;
            int gcol = aq * 4;
            aReg[i] = (grow < M && gcol < K)
                      ? *(const float4*)(A + (size_t)grow * K + gcol)
                      : make_float4(0.f, 0.f, 0.f, 0.f);
        }
    }

    for (int ch = 0; ch < nCh; ch++) {
        int p = ch & 1;
        __half* Ap = As + p * TILE_H;
        __half* Bhp = Bh + p * TILE_H;
        __half* Blp = Bl + p * TILE_H;

        // store prefetched A regs -> smem (convert to fp16)
#pragma unroll
        for (int i = 0; i < 4; i++) {
            int r = ar + i * 32;
            __half2 h01 = __floats2half2_rn(aReg[i].x, aReg[i].y);
            __half2 h23 = __floats2half2_rn(aReg[i].z, aReg[i].w);
            *(__half2*)(Ap + r * LDH + aq * 4)     = h01;
            *(__half2*)(Ap + r * LDH + aq * 4 + 2) = h23;
        }

        cp_wait_all();          // B(ch) landed
        __syncthreads();        // A stores visible; prev MMA reads done

        // prefetch next chunk
        if (ch + 1 < nCh) {
            int kc = (ch + 1) << 5;
            int pn = p ^ 1;
            uint32_t sBhN = sBh + (uint32_t)(pn * TILE_H) * 2;
            uint32_t sBlN = sBl + (uint32_t)(pn * TILE_H) * 2;
#pragma unroll
            for (int i = 0; i < 2; i++) {
                int n = bn + i * 64;
                const __half* srcH = BHg + (size_t)(blockCol + n) * Kpad + kc + bu * 8;
                const __half* srcL = BLg + (size_t)(blockCol + n) * Kpad + kc + bu * 8;
                uint32_t off = (uint32_t)(n * LDH + bu * 8) * 2;
                cp_async16(sBhN + off, srcH);
                cp_async16(sBlN + off, srcL);
            }
            cp_commit();
#pragma unroll
            for (int i = 0; i < 4; i++) {
                int r = ar + i * 32;
                int grow = blockRow + r;
                int gcol = kc + aq * 4;
                aReg[i] = (grow < M && gcol < K)
                          ? *(const float4*)(A + (size_t)grow * K + gcol)
                          : make_float4(0.f, 0.f, 0.f, 0.f);
            }
        }

        // MMA on buffer p: 2 k-frags x (2m x 4n) x 2 B-parts
#pragma unroll
        for (int kk = 0; kk < 2; kk++) {
            wmma::fragment<wmma::matrix_a, 16, 16, 16, __half, wmma::row_major> a0, a1;
            wmma::load_matrix_sync(a0, Ap + (wm)      * LDH + kk * 16, LDH);
            wmma::load_matrix_sync(a1, Ap + (wm + 16) * LDH + kk * 16, LDH);
#pragma unroll
            for (int j = 0; j < 4; j++) {
                wmma::fragment<wmma::matrix_b, 16, 16, 16, __half, wmma::col_major> fbh, fbl;
                wmma::load_matrix_sync(fbh, Bhp + (wn + j * 16) * LDH + kk * 16, LDH);
                wmma::load_matrix_sync(fbl, Blp + (wn + j * 16) * LDH + kk * 16, LDH);
                wmma::mma_sync(c[0][j], a0, fbh, c[0][j]);
                wmma::mma_sync(c[1][j], a1, fbh, c[1][j]);
                wmma::mma_sync(c[0][j], a0, fbl, c[0][j]);
                wmma::mma_sync(c[1][j], a1, fbl, c[1][j]);
            }
        }
    }

    // ---- epilogue ----
    if (interior) {
#pragma unroll
        for (int i = 0; i < 2; i++)
#pragma unroll
            for (int j = 0; j < 4; j++)
                wmma::store_matrix_sync(
                    out + (size_t)(blockRow + wm + i * 16) * OUTW
                        + blockCol + wn + j * 16,
                    c[i][j], OUTW, wmma::mem_row_major);
    } else {
        __syncthreads();
        float* stg = (float*)sm + wid * 256;
#pragma unroll
        for (int i = 0; i < 2; i++)
#pragma unroll
            for (int j = 0; j < 4; j++) {
                wmma::store_matrix_sync(stg, c[i][j], 16, wmma::mem_row_major);
                __syncwarp();
#pragma unroll
                for (int e = 0; e < 8; e++) {
                    int el = lane + e * 32;
                    int r  = el >> 4;
                    int cc = el & 15;
                    int grow = blockRow + wm + i * 16 + r;
                    if (grow < M) {
                        int gc = blockCol + wn + j * 16 + cc;
                        out[(size_t)grow * OUTW + gc] =
                            stg[el] + base[(size_t)grow * OUTW + gc];
                    }
                }
                __syncwarp();
            }
    }
}

// ---------------------------------------------------------------------------
// Launch
// ---------------------------------------------------------------------------
extern "C" void kernel_launch(void* const* d_in, const int* in_sizes, int n_in,
                              void* d_out, int out_size) {
    const float* ue0  = (const float*)d_in[0];
    const float* ie0  = (const float*)d_in[1];
    const float* gcW0 = (const float*)d_in[2];
    const float* gcb0 = (const float*)d_in[3];
    const float* biW0 = (const float*)d_in[4];
    const float* bib0 = (const float*)d_in[5];
    const float* ue1  = (const float*)d_in[6];
    const float* ie1  = (const float*)d_in[7];
    const float* gcW1 = (const float*)d_in[8];
    const float* gcb1 = (const float*)d_in[9];
    const float* biW1 = (const float*)d_in[10];
    const float* bib1 = (const float*)d_in[11];
    const float* mapu = (const float*)d_in[12];
    const float* mapi = (const float*)d_in[13];
    const float* vals0 = (const float*)d_in[14];
    const float* vals1 = (const float*)d_in[15];
    const int*   rows0 = (const int*)d_in[16];
    const int*   cols0 = (const int*)d_in[17];
    const int*   rows1 = (const int*)d_in[18];
    const int*   cols1 = (const int*)d_in[19];
    float* out = (float*)d_out;

    int E0 = in_sizes[14];
    int E1 = in_sizes[15];

    float *ego0, *side0, *alle0, *ego1, *side1, *alle1;
    cudaGetSymbolAddress((void**)&ego0,  g_ego0);
    cudaGetSymbolAddress((void**)&side0, g_side0);
    cudaGetSymbolAddress((void**)&alle0, g_alle0);
    cudaGetSymbolAddress((void**)&ego1,  g_ego1);
    cudaGetSymbolAddress((void**)&side1, g_side1);
    cudaGetSymbolAddress((void**)&alle1, g_alle1);

    __half *bhu, *blu, *bhi, *bli;
    cudaGetSymbolAddress((void**)&bhu, g_Bh_u);
    cudaGetSymbolAddress((void**)&blu, g_Bl_u);
    cudaGetSymbolAddress((void**)&bhi, g_Bh_i);
    cudaGetSymbolAddress((void**)&bli, g_Bl_i);

    const int gemm_smem = 6 * TILE_H * sizeof(__half);   // 61440
    cudaFuncSetAttribute(wmma_gemm_kernel,
                         cudaFuncAttributeMaxDynamicSharedMemorySize,
                         gemm_smem);

    // init
    init_kernel<<<(N0 * DEMB + 255) / 256, 256>>>(ue0, ie0, ego0, alle0, NU0, N0);
    init_kernel<<<(N1 * DEMB + 255) / 256, 256>>>(ue1, ie1, ego1, alle1, NU1, N1);

    for (int l = 0; l < NLAYERS; l++) {
        zero4_kernel<<<(N0 * 16 + 255) / 256, 256>>>((float4*)side0, N0 * 16);
        scatter_kernel<<<((long long)E0 * 16 + 255) / 256, 256>>>(
            rows0, cols0, vals0, ego0, side0, E0);
        layer_kernel<<<(N0 + 15) / 16, 256>>>(
            gcW0, gcb0, biW0, bib0, side0, ego0, alle0, N0, l);

        zero4_kernel<<<(N1 * 16 + 255) / 256, 256>>>((float4*)side1, N1 * 16);
        scatter_kernel<<<((long long)E1 * 16 + 255) / 256, 256>>>(
            rows1, cols1, vals1, ego1, side1, E1);
        layer_kernel<<<(N1 + 15) / 16, 256>>>(
            gcW1, gcb1, biW1, bib1, side1, ego1, alle1, N1, l);
    }

    // pre-split/transpose B operands
    convertB_kernel<<<KPAD_U, 256>>>(alle1, NU1, KPAD_U, bhu, blu);
    convertB_kernel<<<KPAD_I, 256>>>(alle1 + (size_t)NU1 * OUTW, NI1, KPAD_I,
                                     bhi, bli);

    // both residual GEMMs in a single launch
    dim3 grid(BLOCKS_U + BLOCKS_I, 2);
    wmma_gemm_kernel<<<grid, 256, gemm_smem>>>(
        mapu, mapi, bhu, blu, bhi, bli,
        alle0, alle0 + (size_t)NU0 * OUTW,
        out, out + (size_t)NU0 * OUTW);
}

// round 5
// speedup vs baseline: 4.5495x; 1.1819x over previous
#include <cuda_runtime.h>
#include <cuda_fp16.h>
#include <mma.h>
#include <cstdint>

using namespace nvcuda;

// ---------------------------------------------------------------------------
// Problem constants
// ---------------------------------------------------------------------------
#define NU0 20000
#define NI0 15000
#define NU1 4000
#define NI1 3000
#define N0  (NU0 + NI0)   // 35000
#define N1  (NU1 + NI1)   // 7000
#define DEMB 64
#define NLAYERS 3
#define OUTW 256          // D*(L+1)

#define KPAD_U 4032       // multiple of 32
#define KPAD_I 3008

#define BLOCKS_U 157      // ceil(20000/128)
#define BLOCKS_I 118      // ceil(15000/128)
#define LBLOCKS0 2188     // ceil(N0/16)
#define LBLOCKS1 438      // ceil(N1/16)

// ---------------------------------------------------------------------------
// Scratch (static device globals)
// ---------------------------------------------------------------------------
__device__ __align__(256) float g_ego0 [N0 * DEMB];
__device__ __align__(256) float g_side0[N0 * DEMB];
__device__ __align__(256) float g_alle0[N0 * OUTW];
__device__ __align__(256) float g_ego1 [N1 * DEMB];
__device__ __align__(256) float g_side1[N1 * DEMB];
__device__ __align__(256) float g_alle1[N1 * OUTW];

// Pre-transposed fp16 B, K-major [256][Kpad], zero-padded.
__device__ __align__(256) __half g_Bh_u[256 * KPAD_U];
__device__ __align__(256) __half g_Bh_i[256 * KPAD_I];

// ---------------------------------------------------------------------------
// init: ego = concat(ue, ie); alle[:, 0:64] = ego
// ---------------------------------------------------------------------------
__global__ void init_kernel(const float* __restrict__ ue,
                            const float* __restrict__ ie,
                            float* __restrict__ ego,
                            float* __restrict__ alle,
                            int n_users, int n_nodes) {
    int i = blockIdx.x * blockDim.x + threadIdx.x;
    if (i >= n_nodes * DEMB) return;
    int n = i >> 6;
    int d = i & 63;
    float v = (n < n_users) ? ue[n * DEMB + d] : ie[(n - n_users) * DEMB + d];
    ego[i] = v;
    alle[n * OUTW + d] = v;
}

// ---------------------------------------------------------------------------
// zero both side buffers in one launch
// ---------------------------------------------------------------------------
__global__ void zero_both_kernel(float4* __restrict__ s0,
                                 float4* __restrict__ s1) {
    int i = blockIdx.x * blockDim.x + threadIdx.x;
    const int n0 = N0 * 16;
    if (i < n0) s0[i] = make_float4(0.f, 0.f, 0.f, 0.f);
    else if (i < n0 + N1 * 16) s1[i - n0] = make_float4(0.f, 0.f, 0.f, 0.f);
}

// ---------------------------------------------------------------------------
// merged scatter for both graphs: 16 threads/edge, red.global.add.v4.f32
// ---------------------------------------------------------------------------
__global__ void scatter_both_kernel(
    const int* __restrict__ rows0, const int* __restrict__ cols0,
    const float* __restrict__ vals0, const float* __restrict__ ego0,
    float* __restrict__ side0, int e0,
    const int* __restrict__ rows1, const int* __restrict__ cols1,
    const float* __restrict__ vals1, const float* __restrict__ ego1,
    float* __restrict__ side1, int e1) {

    int t = blockIdx.x * blockDim.x + threadIdx.x;
    int e = t >> 4;
    int c = t & 15;
    const int* rows; const int* cols; const float* vals;
    const float* ego; float* side;
    if (e < e0) {
        rows = rows0; cols = cols0; vals = vals0; ego = ego0; side = side0;
    } else {
        e -= e0;
        if (e >= e1) return;
        rows = rows1; cols = cols1; vals = vals1; ego = ego1; side = side1;
    }
    int   col = cols[e];
    int   row = rows[e];
    float v   = vals[e];
    float4 x = ((const float4*)ego)[col * 16 + c];
    float4 y = make_float4(v * x.x, v * x.y, v * x.z, v * x.w);
    float* dst = side + row * DEMB + c * 4;
    asm volatile("red.global.add.v4.f32 [%0], {%1, %2, %3, %4};"
                 :: "l"(dst), "f"(y.x), "f"(y.y), "f"(y.z), "f"(y.w)
                 : "memory");
}

// ---------------------------------------------------------------------------
// merged layer kernel for both graphs
// ---------------------------------------------------------------------------
__global__ __launch_bounds__(256) void layer_both_kernel(
    const float* __restrict__ gcW0, const float* __restrict__ gcb0,
    const float* __restrict__ biW0, const float* __restrict__ bib0,
    const float* __restrict__ side0g,
    float* __restrict__ ego0g, float* __restrict__ alle0g,
    const float* __restrict__ gcW1, const float* __restrict__ gcb1,
    const float* __restrict__ biW1, const float* __restrict__ bib1,
    const float* __restrict__ side1g,
    float* __restrict__ ego1g, float* __restrict__ alle1g,
    int layer) {

    __shared__ float4 sGW[64 * 16];
    __shared__ float4 sBW[64 * 16];
    __shared__ float  sx [16 * 64];
    __shared__ float  sex[16 * 64];

    bool g0 = blockIdx.x < LBLOCKS0;
    const float* gcW  = g0 ? gcW0 : gcW1;
    const float* gcb  = g0 ? gcb0 : gcb1;
    const float* biW  = g0 ? biW0 : biW1;
    const float* bib  = g0 ? bib0 : bib1;
    const float* side = g0 ? side0g : side1g;
    float* ego  = g0 ? ego0g : ego1g;
    float* alle = g0 ? alle0g : alle1g;
    int n_nodes = g0 ? N0 : N1;
    int blk     = g0 ? blockIdx.x : blockIdx.x - LBLOCKS0;

    int tid = threadIdx.x;

    const float4* gW4 = (const float4*)(gcW + layer * 64 * 64);
    const float4* bW4 = (const float4*)(biW + layer * 64 * 64);
#pragma unroll
    for (int i = 0; i < 4; i++) {
        sGW[tid + i * 256] = gW4[tid + i * 256];
        sBW[tid + i * 256] = bW4[tid + i * 256];
    }

    int nl = tid >> 4;
    int q  = tid & 15;
    int node = blk * 16 + nl;
    bool valid = node < n_nodes;

    float4 x4 = valid ? ((const float4*)side)[node * 16 + q] : make_float4(0,0,0,0);
    float4 e4 = valid ? ((const float4*)ego )[node * 16 + q] : make_float4(0,0,0,0);
    sx [nl * 64 + q * 4 + 0] = x4.x;
    sx [nl * 64 + q * 4 + 1] = x4.y;
    sx [nl * 64 + q * 4 + 2] = x4.z;
    sx [nl * 64 + q * 4 + 3] = x4.w;
    sex[nl * 64 + q * 4 + 0] = e4.x * x4.x;
    sex[nl * 64 + q * 4 + 1] = e4.y * x4.y;
    sex[nl * 64 + q * 4 + 2] = e4.z * x4.z;
    sex[nl * 64 + q * 4 + 3] = e4.w * x4.w;
    __syncthreads();

    float4 a = ((const float4*)(gcb + layer * 64))[q];
    float4 b = ((const float4*)(bib + layer * 64))[q];

#pragma unroll
    for (int k = 0; k < 64; k++) {
        float  xk  = sx [nl * 64 + k];
        float  exk = sex[nl * 64 + k];
        float4 wg  = sGW[k * 16 + q];
        float4 wb  = sBW[k * 16 + q];
        a.x += xk * wg.x;  a.y += xk * wg.y;  a.z += xk * wg.z;  a.w += xk * wg.w;
        b.x += exk * wb.x; b.y += exk * wb.y; b.z += exk * wb.z; b.w += exk * wb.w;
    }

    a.x = a.x > 0.f ? a.x : 0.01f * a.x;
    a.y = a.y > 0.f ? a.y : 0.01f * a.y;
    a.z = a.z > 0.f ? a.z : 0.01f * a.z;
    a.w = a.w > 0.f ? a.w : 0.01f * a.w;
    b.x = b.x > 0.f ? b.x : 0.01f * b.x;
    b.y = b.y > 0.f ? b.y : 0.01f * b.y;
    b.z = b.z > 0.f ? b.z : 0.01f * b.z;
    b.w = b.w > 0.f ? b.w : 0.01f * b.w;

    float4 eg;
    eg.x = a.x + b.x; eg.y = a.y + b.y; eg.z = a.z + b.z; eg.w = a.w + b.w;

    float ss = eg.x * eg.x + eg.y * eg.y + eg.z * eg.z + eg.w * eg.w;
#pragma unroll
    for (int off = 8; off > 0; off >>= 1)
        ss += __shfl_xor_sync(0xffffffffu, ss, off);

    float r = 1.0f / fmaxf(sqrtf(ss), 1e-12f);

    if (valid) {
        ((float4*)ego)[node * 16 + q] = eg;
        float4 nrm = make_float4(eg.x * r, eg.y * r, eg.z * r, eg.w * r);
        ((float4*)(alle + node * OUTW + (layer + 1) * 64))[q] = nrm;
    }
}

// ---------------------------------------------------------------------------
// convertB: Bh[n][k] = fp16(B[k][n]) (K-major, zero-padded)
// ---------------------------------------------------------------------------
__global__ void convertB_kernel(const float* __restrict__ B, int K, int Kpad,
                                __half* __restrict__ hi) {
    int idx = blockIdx.x * blockDim.x + threadIdx.x;
    if (idx >= 256 * Kpad) return;
    int n = idx & 255;
    int k = idx >> 8;
    float v = (k < K) ? B[(size_t)k * 256 + n] : 0.f;
    hi[(size_t)n * Kpad + k] = __float2half_rn(v);
}

// ---------------------------------------------------------------------------
// fp16 WMMA GEMM + residual, single pass, cp.async double-buffered.
//   out[M,256] = base[M,256] + A[M,K] @ B[K,256]
// CTA tile: 128 rows x 256 cols (A read exactly once). 8 warps, 64x64 each.
// ---------------------------------------------------------------------------
#define LDH 40               // smem leading dim in halves (80B rows)
#define A_TILE (128 * LDH)   // halves per A buffer
#define B_TILE (256 * LDH)   // halves per B buffer

__device__ __forceinline__ void cp_async16(uint32_t saddr, const void* gptr) {
    asm volatile("cp.async.cg.shared.global [%0], [%1], 16;"
                 :: "r"(saddr), "l"(gptr));
}
__device__ __forceinline__ void cp_commit() {
    asm volatile("cp.async.commit_group;");
}
__device__ __forceinline__ void cp_wait_all() {
    asm volatile("cp.async.wait_group 0;" ::: "memory");
}

__global__ __launch_bounds__(256, 1) void wmma_gemm_kernel(
    const float* __restrict__ Au, const float* __restrict__ Ai,
    const __half* __restrict__ Bhu, const __half* __restrict__ Bhi,
    const float* __restrict__ baseU, const float* __restrict__ baseI,
    float* __restrict__ outU, float* __restrict__ outI) {

    extern __shared__ __half sm[];
    __half* As = sm;                  // [2][128][LDH]
    __half* Bs = sm + 2 * A_TILE;     // [2][256][LDH]

    bool isU = blockIdx.x < BLOCKS_U;
    const float*  A    = isU ? Au    : Ai;
    const __half* BHg  = isU ? Bhu   : Bhi;
    const float*  base = isU ? baseU : baseI;
    float*        out  = isU ? outU  : outI;
    int M    = isU ? NU0 : NI0;
    int K    = isU ? NU1 : NI1;
    int Kpad = isU ? KPAD_U : KPAD_I;
    int blockRow = (isU ? blockIdx.x : blockIdx.x - BLOCKS_U) * 128;

    int tid  = threadIdx.x;
    int wid  = tid >> 5;
    int lane = tid & 31;
    int wm = (wid >> 2) * 64;     // 0 or 64
    int wn = (wid & 3) * 64;      // 0,64,128,192

    bool interior = (blockRow + 128 <= M);

    // A-load mapping: 4 float4 per thread per chunk (128 rows x 32 cols)
    int ar = tid >> 3;            // 0..31 (rows +i*32)
    int aq = tid & 7;             // float4 index within 32-col row
    // B-load mapping: 4 x 16B units per chunk (256 rows x 64B)
    int bn = tid >> 2;            // 0..63 (rows +i*64)
    int bu = tid & 3;             // 16B unit within row

    uint32_t sBs = (uint32_t)__cvta_generic_to_shared(Bs);

    wmma::fragment<wmma::accumulator, 16, 16, 16, float> c[4][4];
    if (interior) {
#pragma unroll
        for (int i = 0; i < 4; i++)
#pragma unroll
            for (int j = 0; j < 4; j++)
                wmma::load_matrix_sync(
                    c[i][j],
                    base + (size_t)(blockRow + wm + i * 16) * OUTW
                         + wn + j * 16,
                    OUTW, wmma::mem_row_major);
    } else {
#pragma unroll
        for (int i = 0; i < 4; i++)
#pragma unroll
            for (int j = 0; j < 4; j++)
                wmma::fill_fragment(c[i][j], 0.f);
    }

    int nCh = Kpad >> 5;
    float4 aReg[4];

    // prologue: B chunk 0 -> buf 0; A chunk 0 -> regs
    {
#pragma unroll
        for (int i = 0; i < 4; i++) {
            int n = bn + i * 64;
            const __half* src = BHg + (size_t)n * Kpad + bu * 8;
            cp_async16(sBs + (uint32_t)(n * LDH + bu * 8) * 2, src);
        }
        cp_commit();
#pragma unroll
        for (int i = 0; i < 4; i++) {
            int r = ar + i * 32;
            int grow = blockRow + r;
            aReg[i] = (grow < M)
                      ? *(const float4*)(A + (size_t)grow * K + aq * 4)
                      : make_float4(0.f, 0.f, 0.f, 0.f);
        }
    }

    for (int ch = 0; ch < nCh; ch++) {
        int p = ch & 1;
        __half* Ap = As + p * A_TILE;
        __half* Bp = Bs + p * B_TILE;

        // store prefetched A regs -> smem (fp16 convert)
#pragma unroll
        for (int i = 0; i < 4; i++) {
            int r = ar + i * 32;
            __half2 h01 = __floats2half2_rn(aReg[i].x, aReg[i].y);
            __half2 h23 = __floats2half2_rn(aReg[i].z, aReg[i].w);
            *(__half2*)(Ap + r * LDH + aq * 4)     = h01;
            *(__half2*)(Ap + r * LDH + aq * 4 + 2) = h23;
        }

        cp_wait_all();     // B(ch) landed
        __syncthreads();   // A stores visible; prior MMA reads complete

        // prefetch next chunk
        if (ch + 1 < nCh) {
            int kc = (ch + 1) << 5;
            uint32_t sBN = sBs + (uint32_t)((p ^ 1) * B_TILE) * 2;
#pragma unroll
            for (int i = 0; i < 4; i++) {
                int n = bn + i * 64;
                const __half* src = BHg + (size_t)n * Kpad + kc + bu * 8;
                cp_async16(sBN + (uint32_t)(n * LDH + bu * 8) * 2, src);
            }
            cp_commit();
#pragma unroll
            for (int i = 0; i < 4; i++) {
                int r = ar + i * 32;
                int grow = blockRow + r;
                int gcol = kc + aq * 4;
                aReg[i] = (grow < M && gcol < K)
                          ? *(const float4*)(A + (size_t)grow * K + gcol)
                          : make_float4(0.f, 0.f, 0.f, 0.f);
            }
        }

        // MMA: 2 k-frags x (4m x 4n)
#pragma unroll
        for (int kk = 0; kk < 2; kk++) {
            wmma::fragment<wmma::matrix_a, 16, 16, 16, __half, wmma::row_major> af[4];
#pragma unroll
            for (int i = 0; i < 4; i++)
                wmma::load_matrix_sync(af[i], Ap + (wm + i * 16) * LDH + kk * 16, LDH);
#pragma unroll
            for (int j = 0; j < 4; j++) {
                wmma::fragment<wmma::matrix_b, 16, 16, 16, __half, wmma::col_major> bf;
                wmma::load_matrix_sync(bf, Bp + (wn + j * 16) * LDH + kk * 16, LDH);
#pragma unroll
                for (int i = 0; i < 4; i++)
                    wmma::mma_sync(c[i][j], af[i], bf, c[i][j]);
            }
        }
    }

    // ---- epilogue ----
    if (interior) {
#pragma unroll
        for (int i = 0; i < 4; i++)
#pragma unroll
            for (int j = 0; j < 4; j++)
                wmma::store_matrix_sync(
                    out + (size_t)(blockRow + wm + i * 16) * OUTW
                        + wn + j * 16,
                    c[i][j], OUTW, wmma::mem_row_major);
    } else {
        __syncthreads();
        float* stg = (float*)sm + wid * 256;   // per-warp 16x16 staging
#pragma unroll
        for (int i = 0; i < 4; i++)
#pragma unroll
            for (int j = 0; j < 4; j++) {
                wmma::store_matrix_sync(stg, c[i][j], 16, wmma::mem_row_major);
                __syncwarp();
#pragma unroll
                for (int e = 0; e < 8; e++) {
                    int el = lane + e * 32;
                    int r  = el >> 4;
                    int cc = el & 15;
                    int grow = blockRow + wm + i * 16 + r;
                    if (grow < M) {
                        int gc = wn + j * 16 + cc;
                        out[(size_t)grow * OUTW + gc] =
                            stg[el] + base[(size_t)grow * OUTW + gc];
                    }
                }
                __syncwarp();
            }
    }
}

// ---------------------------------------------------------------------------
// Launch
// ---------------------------------------------------------------------------
extern "C" void kernel_launch(void* const* d_in, const int* in_sizes, int n_in,
                              void* d_out, int out_size) {
    const float* ue0  = (const float*)d_in[0];
    const float* ie0  = (const float*)d_in[1];
    const float* gcW0 = (const float*)d_in[2];
    const float* gcb0 = (const float*)d_in[3];
    const float* biW0 = (const float*)d_in[4];
    const float* bib0 = (const float*)d_in[5];
    const float* ue1  = (const float*)d_in[6];
    const float* ie1  = (const float*)d_in[7];
    const float* gcW1 = (const float*)d_in[8];
    const float* gcb1 = (const float*)d_in[9];
    const float* biW1 = (const float*)d_in[10];
    const float* bib1 = (const float*)d_in[11];
    const float* mapu = (const float*)d_in[12];
    const float* mapi = (const float*)d_in[13];
    const float* vals0 = (const float*)d_in[14];
    const float* vals1 = (const float*)d_in[15];
    const int*   rows0 = (const int*)d_in[16];
    const int*   cols0 = (const int*)d_in[17];
    const int*   rows1 = (const int*)d_in[18];
    const int*   cols1 = (const int*)d_in[19];
    float* out = (float*)d_out;

    int E0 = in_sizes[14];
    int E1 = in_sizes[15];

    float *ego0, *side0, *alle0, *ego1, *side1, *alle1;
    cudaGetSymbolAddress((void**)&ego0,  g_ego0);
    cudaGetSymbolAddress((void**)&side0, g_side0);
    cudaGetSymbolAddress((void**)&alle0, g_alle0);
    cudaGetSymbolAddress((void**)&ego1,  g_ego1);
    cudaGetSymbolAddress((void**)&side1, g_side1);
    cudaGetSymbolAddress((void**)&alle1, g_alle1);

    __half *bhu, *bhi;
    cudaGetSymbolAddress((void**)&bhu, g_Bh_u);
    cudaGetSymbolAddress((void**)&bhi, g_Bh_i);

    const int gemm_smem = (2 * A_TILE + 2 * B_TILE) * sizeof(__half); // 61440
    cudaFuncSetAttribute(wmma_gemm_kernel,
                         cudaFuncAttributeMaxDynamicSharedMemorySize,
                         gemm_smem);

    // init
    init_kernel<<<(N0 * DEMB + 255) / 256, 256>>>(ue0, ie0, ego0, alle0, NU0, N0);
    init_kernel<<<(N1 * DEMB + 255) / 256, 256>>>(ue1, ie1, ego1, alle1, NU1, N1);

    int zeroBlocks = ((N0 + N1) * 16 + 255) / 256;
    long long scatterThreads = (long long)(E0 + E1) * 16;
    int scatterBlocks = (int)((scatterThreads + 255) / 256);

    for (int l = 0; l < NLAYERS; l++) {
        zero_both_kernel<<<zeroBlocks, 256>>>((float4*)side0, (float4*)side1);
        scatter_both_kernel<<<scatterBlocks, 256>>>(
            rows0, cols0, vals0, ego0, side0, E0,
            rows1, cols1, vals1, ego1, side1, E1);
        layer_both_kernel<<<LBLOCKS0 + LBLOCKS1, 256>>>(
            gcW0, gcb0, biW0, bib0, side0, ego0, alle0,
            gcW1, gcb1, biW1, bib1, side1, ego1, alle1, l);
    }

    // pre-transpose/convert B operands (fp16 single pass)
    convertB_kernel<<<KPAD_U, 256>>>(alle1, NU1, KPAD_U, bhu);
    convertB_kernel<<<KPAD_I, 256>>>(alle1 + (size_t)NU1 * OUTW, NI1, KPAD_I, bhi);

    // both residual GEMMs in a single launch (full-N tiles, A read once)
    wmma_gemm_kernel<<<BLOCKS_U + BLOCKS_I, 256, gemm_smem>>>(
        mapu, mapi, bhu, bhi,
        alle0, alle0 + (size_t)NU0 * OUTW,
        out, out + (size_t)NU0 * OUTW);
}

// round 6
// speedup vs baseline: 4.9065x; 1.0785x over previous
#include <cuda_runtime.h>
#include <cuda_fp16.h>
#include <mma.h>
#include <cstdint>

using namespace nvcuda;

// ---------------------------------------------------------------------------
// Problem constants
// ---------------------------------------------------------------------------
#define NU0 20000
#define NI0 15000
#define NU1 4000
#define NI1 3000
#define N0  (NU0 + NI0)   // 35000
#define N1  (NU1 + NI1)   // 7000
#define DEMB 64
#define NLAYERS 3
#define OUTW 256          // D*(L+1)

#define KPAD_U 4032       // multiple of 64
#define KPAD_I 3008       // multiple of 64

#define BLOCKS_U 157      // ceil(20000/128)
#define BLOCKS_I 118      // ceil(15000/128)
#define LBLOCKS0 2188     // ceil(N0/16)
#define LBLOCKS1 438      // ceil(N1/16)

// ---------------------------------------------------------------------------
// Scratch (static device globals)
// ---------------------------------------------------------------------------
__device__ __align__(256) float g_ego0 [N0 * DEMB];
__device__ __align__(256) float g_side0[N0 * DEMB];
__device__ __align__(256) float g_alle0[N0 * OUTW];
__device__ __align__(256) float g_ego1 [N1 * DEMB];
__device__ __align__(256) float g_side1[N1 * DEMB];
__device__ __align__(256) float g_alle1[N1 * OUTW];

// Pre-transposed fp16 B, K-major [256][Kpad], zero-padded.
__device__ __align__(256) __half g_Bh_u[256 * KPAD_U];
__device__ __align__(256) __half g_Bh_i[256 * KPAD_I];

// ---------------------------------------------------------------------------
// init both graphs: ego = concat(ue, ie); alle[:,0:64] = ego; side = 0
// ---------------------------------------------------------------------------
__global__ void init_both_kernel(const float* __restrict__ ue0,
                                 const float* __restrict__ ie0,
                                 const float* __restrict__ ue1,
                                 const float* __restrict__ ie1,
                                 float* __restrict__ ego0,
                                 float* __restrict__ alle0,
                                 float* __restrict__ side0,
                                 float* __restrict__ ego1,
                                 float* __restrict__ alle1,
                                 float* __restrict__ side1) {
    int i = blockIdx.x * blockDim.x + threadIdx.x;
    const float* ue; const float* ie;
    float *ego, *alle, *side;
    int n_users;
    if (i < N0 * DEMB) {
        ue = ue0; ie = ie0; ego = ego0; alle = alle0; side = side0;
        n_users = NU0;
    } else {
        i -= N0 * DEMB;
        if (i >= N1 * DEMB) return;
        ue = ue1; ie = ie1; ego = ego1; alle = alle1; side = side1;
        n_users = NU1;
    }
    int n = i >> 6;
    int d = i & 63;
    float v = (n < n_users) ? ue[n * DEMB + d] : ie[(n - n_users) * DEMB + d];
    ego[i] = v;
    side[i] = 0.f;
    alle[n * OUTW + d] = v;
}

// ---------------------------------------------------------------------------
// merged scatter for both graphs: 16 threads/edge, red.global.add.v4.f32
// ---------------------------------------------------------------------------
__global__ void scatter_both_kernel(
    const int* __restrict__ rows0, const int* __restrict__ cols0,
    const float* __restrict__ vals0, const float* __restrict__ ego0,
    float* __restrict__ side0, int e0,
    const int* __restrict__ rows1, const int* __restrict__ cols1,
    const float* __restrict__ vals1, const float* __restrict__ ego1,
    float* __restrict__ side1, int e1) {

    int t = blockIdx.x * blockDim.x + threadIdx.x;
    int e = t >> 4;
    int c = t & 15;
    const int* rows; const int* cols; const float* vals;
    const float* ego; float* side;
    if (e < e0) {
        rows = rows0; cols = cols0; vals = vals0; ego = ego0; side = side0;
    } else {
        e -= e0;
        if (e >= e1) return;
        rows = rows1; cols = cols1; vals = vals1; ego = ego1; side = side1;
    }
    int   col = cols[e];
    int   row = rows[e];
    float v   = vals[e];
    float4 x = ((const float4*)ego)[col * 16 + c];
    float4 y = make_float4(v * x.x, v * x.y, v * x.z, v * x.w);
    float* dst = side + row * DEMB + c * 4;
    asm volatile("red.global.add.v4.f32 [%0], {%1, %2, %3, %4};"
                 :: "l"(dst), "f"(y.x), "f"(y.y), "f"(y.z), "f"(y.w)
                 : "memory");
}

// ---------------------------------------------------------------------------
// merged layer kernel; also re-zeroes side for the next scatter (layer<2)
// ---------------------------------------------------------------------------
__global__ __launch_bounds__(256) void layer_both_kernel(
    const float* __restrict__ gcW0, const float* __restrict__ gcb0,
    const float* __restrict__ biW0, const float* __restrict__ bib0,
    float* __restrict__ side0g,
    float* __restrict__ ego0g, float* __restrict__ alle0g,
    const float* __restrict__ gcW1, const float* __restrict__ gcb1,
    const float* __restrict__ biW1, const float* __restrict__ bib1,
    float* __restrict__ side1g,
    float* __restrict__ ego1g, float* __restrict__ alle1g,
    int layer) {

    __shared__ float4 sGW[64 * 16];
    __shared__ float4 sBW[64 * 16];
    __shared__ float  sx [16 * 64];
    __shared__ float  sex[16 * 64];

    bool g0 = blockIdx.x < LBLOCKS0;
    const float* gcW  = g0 ? gcW0 : gcW1;
    const float* gcb  = g0 ? gcb0 : gcb1;
    const float* biW  = g0 ? biW0 : biW1;
    const float* bib  = g0 ? bib0 : bib1;
    float* side = g0 ? side0g : side1g;
    float* ego  = g0 ? ego0g : ego1g;
    float* alle = g0 ? alle0g : alle1g;
    int n_nodes = g0 ? N0 : N1;
    int blk     = g0 ? blockIdx.x : blockIdx.x - LBLOCKS0;

    int tid = threadIdx.x;

    const float4* gW4 = (const float4*)(gcW + layer * 64 * 64);
    const float4* bW4 = (const float4*)(biW + layer * 64 * 64);
#pragma unroll
    for (int i = 0; i < 4; i++) {
        sGW[tid + i * 256] = gW4[tid + i * 256];
        sBW[tid + i * 256] = bW4[tid + i * 256];
    }

    int nl = tid >> 4;
    int q  = tid & 15;
    int node = blk * 16 + nl;
    bool valid = node < n_nodes;

    float4 x4 = valid ? ((const float4*)side)[node * 16 + q] : make_float4(0,0,0,0);
    float4 e4 = valid ? ((const float4*)ego )[node * 16 + q] : make_float4(0,0,0,0);

    // re-zero side for the next layer's scatter (one pass saved)
    if (valid && layer < NLAYERS - 1)
        ((float4*)side)[node * 16 + q] = make_float4(0.f, 0.f, 0.f, 0.f);

    sx [nl * 64 + q * 4 + 0] = x4.x;
    sx [nl * 64 + q * 4 + 1] = x4.y;
    sx [nl * 64 + q * 4 + 2] = x4.z;
    sx [nl * 64 + q * 4 + 3] = x4.w;
    sex[nl * 64 + q * 4 + 0] = e4.x * x4.x;
    sex[nl * 64 + q * 4 + 1] = e4.y * x4.y;
    sex[nl * 64 + q * 4 + 2] = e4.z * x4.z;
    sex[nl * 64 + q * 4 + 3] = e4.w * x4.w;
    __syncthreads();

    float4 a = ((const float4*)(gcb + layer * 64))[q];
    float4 b = ((const float4*)(bib + layer * 64))[q];

#pragma unroll
    for (int k = 0; k < 64; k++) {
        float  xk  = sx [nl * 64 + k];
        float  exk = sex[nl * 64 + k];
        float4 wg  = sGW[k * 16 + q];
        float4 wb  = sBW[k * 16 + q];
        a.x += xk * wg.x;  a.y += xk * wg.y;  a.z += xk * wg.z;  a.w += xk * wg.w;
        b.x += exk * wb.x; b.y += exk * wb.y; b.z += exk * wb.z; b.w += exk * wb.w;
    }

    a.x = a.x > 0.f ? a.x : 0.01f * a.x;
    a.y = a.y > 0.f ? a.y : 0.01f * a.y;
    a.z = a.z > 0.f ? a.z : 0.01f * a.z;
    a.w = a.w > 0.f ? a.w : 0.01f * a.w;
    b.x = b.x > 0.f ? b.x : 0.01f * b.x;
    b.y = b.y > 0.f ? b.y : 0.01f * b.y;
    b.z = b.z > 0.f ? b.z : 0.01f * b.z;
    b.w = b.w > 0.f ? b.w : 0.01f * b.w;

    float4 eg;
    eg.x = a.x + b.x; eg.y = a.y + b.y; eg.z = a.z + b.z; eg.w = a.w + b.w;

    float ss = eg.x * eg.x + eg.y * eg.y + eg.z * eg.z + eg.w * eg.w;
#pragma unroll
    for (int off = 8; off > 0; off >>= 1)
        ss += __shfl_xor_sync(0xffffffffu, ss, off);

    float r = 1.0f / fmaxf(sqrtf(ss), 1e-12f);

    if (valid) {
        ((float4*)ego)[node * 16 + q] = eg;
        float4 nrm = make_float4(eg.x * r, eg.y * r, eg.z * r, eg.w * r);
        ((float4*)(alle + node * OUTW + (layer + 1) * 64))[q] = nrm;
    }
}

// ---------------------------------------------------------------------------
// convert both B operands: Bh[n][k] = fp16(B[k][n]) (K-major, zero-padded)
// ---------------------------------------------------------------------------
__global__ void convertB_both_kernel(const float* __restrict__ Bu,
                                     const float* __restrict__ Bi,
                                     __half* __restrict__ hu,
                                     __half* __restrict__ hi) {
    int idx = blockIdx.x * blockDim.x + threadIdx.x;
    const float* B; __half* h; int K, Kpad;
    if (idx < 256 * KPAD_U) {
        B = Bu; h = hu; K = NU1; Kpad = KPAD_U;
    } else {
        idx -= 256 * KPAD_U;
        if (idx >= 256 * KPAD_I) return;
        B = Bi; h = hi; K = NI1; Kpad = KPAD_I;
    }
    int n = idx & 255;
    int k = idx >> 8;
    float v = (k < K) ? B[(size_t)k * 256 + n] : 0.f;
    h[(size_t)n * Kpad + k] = __float2half_rn(v);
}

// ---------------------------------------------------------------------------
// fp16 WMMA GEMM + residual, single pass, cp.async double-buffered, BK=64.
//   out[M,256] = base[M,256] + A[M,K] @ B[K,256]
// CTA tile: 128 rows x 256 cols (A read exactly once). 8 warps, 64x64 each.
// ---------------------------------------------------------------------------
#define LDH 72               // smem leading dim in halves (144B rows)
#define A_TILE (128 * LDH)   // halves per A buffer
#define B_TILE (256 * LDH)   // halves per B buffer

__device__ __forceinline__ void cp_async16(uint32_t saddr, const void* gptr) {
    asm volatile("cp.async.cg.shared.global [%0], [%1], 16;"
                 :: "r"(saddr), "l"(gptr));
}
__device__ __forceinline__ void cp_commit() {
    asm volatile("cp.async.commit_group;");
}
__device__ __forceinline__ void cp_wait_all() {
    asm volatile("cp.async.wait_group 0;" ::: "memory");
}

__global__ __launch_bounds__(256, 1) void wmma_gemm_kernel(
    const float* __restrict__ Au, const float* __restrict__ Ai,
    const __half* __restrict__ Bhu, const __half* __restrict__ Bhi,
    const float* __restrict__ baseU, const float* __restrict__ baseI,
    float* __restrict__ outU, float* __restrict__ outI) {

    extern __shared__ __half sm[];
    __half* As = sm;                  // [2][128][LDH]
    __half* Bs = sm + 2 * A_TILE;     // [2][256][LDH]

    bool isU = blockIdx.x < BLOCKS_U;
    const float*  A    = isU ? Au    : Ai;
    const __half* BHg  = isU ? Bhu   : Bhi;
    const float*  base = isU ? baseU : baseI;
    float*        out  = isU ? outU  : outI;
    int M    = isU ? NU0 : NI0;
    int K    = isU ? NU1 : NI1;
    int Kpad = isU ? KPAD_U : KPAD_I;
    int blockRow = (isU ? blockIdx.x : blockIdx.x - BLOCKS_U) * 128;

    int tid  = threadIdx.x;
    int wid  = tid >> 5;
    int lane = tid & 31;
    int wm = (wid >> 2) * 64;     // 0 or 64
    int wn = (wid & 3) * 64;      // 0,64,128,192

    bool interior = (blockRow + 128 <= M);

    // A-load mapping: 8 float4 per thread per chunk (128 rows x 64 cols)
    int ar = tid >> 4;            // 0..15 (rows +i*16)
    int aq = tid & 15;            // float4 index within 64-col row
    // B-load mapping: 8 x 16B units per chunk (256 rows x 128B)
    int bn = tid >> 3;            // 0..31 (rows +i*32)
    int bu = tid & 7;             // 16B unit within row

    uint32_t sBs = (uint32_t)__cvta_generic_to_shared(Bs);

    wmma::fragment<wmma::accumulator, 16, 16, 16, float> c[4][4];
    if (interior) {
#pragma unroll
        for (int i = 0; i < 4; i++)
#pragma unroll
            for (int j = 0; j < 4; j++)
                wmma::load_matrix_sync(
                    c[i][j],
                    base + (size_t)(blockRow + wm + i * 16) * OUTW
                         + wn + j * 16,
                    OUTW, wmma::mem_row_major);
    } else {
#pragma unroll
        for (int i = 0; i < 4; i++)
#pragma unroll
            for (int j = 0; j < 4; j++)
                wmma::fill_fragment(c[i][j], 0.f);
    }

    int nCh = Kpad >> 6;
    float4 aReg[8];

    // prologue: B chunk 0 -> buf 0; A chunk 0 -> regs
    {
#pragma unroll
        for (int i = 0; i < 8; i++) {
            int n = bn + i * 32;
            const __half* src = BHg + (size_t)n * Kpad + bu * 8;
            cp_async16(sBs + (uint32_t)(n * LDH + bu * 8) * 2, src);
        }
        cp_commit();
#pragma unroll
        for (int i = 0; i < 8; i++) {
            int r = ar + i * 16;
            int grow = blockRow + r;
            int gcol = aq * 4;
            aReg[i] = (grow < M && gcol < K)
                      ? *(const float4*)(A + (size_t)grow * K + gcol)
                      : make_float4(0.f, 0.f, 0.f, 0.f);
        }
    }

    for (int ch = 0; ch < nCh; ch++) {
        int p = ch & 1;
        __half* Ap = As + p * A_TILE;
        __half* Bp = Bs + p * B_TILE;

        // store prefetched A regs -> smem (fp16 convert)
#pragma unroll
        for (int i = 0; i < 8; i++) {
            int r = ar + i * 16;
            __half2 h01 = __floats2half2_rn(aReg[i].x, aReg[i].y);
            __half2 h23 = __floats2half2_rn(aReg[i].z, aReg[i].w);
            *(__half2*)(Ap + r * LDH + aq * 4)     = h01;
            *(__half2*)(Ap + r * LDH + aq * 4 + 2) = h23;
        }

        cp_wait_all();     // B(ch) landed
        __syncthreads();   // A stores visible; prior MMA reads complete

        // prefetch next chunk (overlaps with this chunk's MMAs)
        if (ch + 1 < nCh) {
            int kc = (ch + 1) << 6;
            uint32_t sBN = sBs + (uint32_t)((p ^ 1) * B_TILE) * 2;
#pragma unroll
            for (int i = 0; i < 8; i++) {
                int n = bn + i * 32;
                const __half* src = BHg + (size_t)n * Kpad + kc + bu * 8;
                cp_async16(sBN + (uint32_t)(n * LDH + bu * 8) * 2, src);
            }
            cp_commit();
#pragma unroll
            for (int i = 0; i < 8; i++) {
                int r = ar + i * 16;
                int grow = blockRow + r;
                int gcol = kc + aq * 4;
                aReg[i] = (grow < M && gcol < K)
                          ? *(const float4*)(A + (size_t)grow * K + gcol)
                          : make_float4(0.f, 0.f, 0.f, 0.f);
            }
        }

        // MMA: 4 k-frags x (4m x 4n)
#pragma unroll
        for (int kk = 0; kk < 4; kk++) {
            wmma::fragment<wmma::matrix_a, 16, 16, 16, __half, wmma::row_major> af[4];
#pragma unroll
            for (int i = 0; i < 4; i++)
                wmma::load_matrix_sync(af[i], Ap + (wm + i * 16) * LDH + kk * 16, LDH);
#pragma unroll
            for (int j = 0; j < 4; j++) {
                wmma::fragment<wmma::matrix_b, 16, 16, 16, __half, wmma::col_major> bf;
                wmma::load_matrix_sync(bf, Bp + (wn + j * 16) * LDH + kk * 16, LDH);
#pragma unroll
                for (int i = 0; i < 4; i++)
                    wmma::mma_sync(c[i][j], af[i], bf, c[i][j]);
            }
        }
    }

    // ---- epilogue ----
    if (interior) {
#pragma unroll
        for (int i = 0; i < 4; i++)
#pragma unroll
            for (int j = 0; j < 4; j++)
                wmma::store_matrix_sync(
                    out + (size_t)(blockRow + wm + i * 16) * OUTW
                        + wn + j * 16,
                    c[i][j], OUTW, wmma::mem_row_major);
    } else {
        __syncthreads();
        float* stg = (float*)sm + wid * 256;   // per-warp 16x16 staging
#pragma unroll
        for (int i = 0; i < 4; i++)
#pragma unroll
            for (int j = 0; j < 4; j++) {
                wmma::store_matrix_sync(stg, c[i][j], 16, wmma::mem_row_major);
                __syncwarp();
#pragma unroll
                for (int e = 0; e < 8; e++) {
                    int el = lane + e * 32;
                    int r  = el >> 4;
                    int cc = el & 15;
                    int grow = blockRow + wm + i * 16 + r;
                    if (grow < M) {
                        int gc = wn + j * 16 + cc;
                        out[(size_t)grow * OUTW + gc] =
                            stg[el] + base[(size_t)grow * OUTW + gc];
                    }
                }
                __syncwarp();
            }
    }
}

// ---------------------------------------------------------------------------
// Launch
// ---------------------------------------------------------------------------
extern "C" void kernel_launch(void* const* d_in, const int* in_sizes, int n_in,
                              void* d_out, int out_size) {
    const float* ue0  = (const float*)d_in[0];
    const float* ie0  = (const float*)d_in[1];
    const float* gcW0 = (const float*)d_in[2];
    const float* gcb0 = (const float*)d_in[3];
    const float* biW0 = (const float*)d_in[4];
    const float* bib0 = (const float*)d_in[5];
    const float* ue1  = (const float*)d_in[6];
    const float* ie1  = (const float*)d_in[7];
    const float* gcW1 = (const float*)d_in[8];
    const float* gcb1 = (const float*)d_in[9];
    const float* biW1 = (const float*)d_in[10];
    const float* bib1 = (const float*)d_in[11];
    const float* mapu = (const float*)d_in[12];
    const float* mapi = (const float*)d_in[13];
    const float* vals0 = (const float*)d_in[14];
    const float* vals1 = (const float*)d_in[15];
    const int*   rows0 = (const int*)d_in[16];
    const int*   cols0 = (const int*)d_in[17];
    const int*   rows1 = (const int*)d_in[18];
    const int*   cols1 = (const int*)d_in[19];
    float* out = (float*)d_out;

    int E0 = in_sizes[14];
    int E1 = in_sizes[15];

    float *ego0, *side0, *alle0, *ego1, *side1, *alle1;
    cudaGetSymbolAddress((void**)&ego0,  g_ego0);
    cudaGetSymbolAddress((void**)&side0, g_side0);
    cudaGetSymbolAddress((void**)&alle0, g_alle0);
    cudaGetSymbolAddress((void**)&ego1,  g_ego1);
    cudaGetSymbolAddress((void**)&side1, g_side1);
    cudaGetSymbolAddress((void**)&alle1, g_alle1);

    __half *bhu, *bhi;
    cudaGetSymbolAddress((void**)&bhu, g_Bh_u);
    cudaGetSymbolAddress((void**)&bhi, g_Bh_i);

    const int gemm_smem = (2 * A_TILE + 2 * B_TILE) * sizeof(__half); // 110592
    cudaFuncSetAttribute(wmma_gemm_kernel,
                         cudaFuncAttributeMaxDynamicSharedMemorySize,
                         gemm_smem);

    // init (both graphs, also zeroes side)
    init_both_kernel<<<((N0 + N1) * DEMB + 255) / 256, 256>>>(
        ue0, ie0, ue1, ie1, ego0, alle0, side0, ego1, alle1, side1);

    long long scatterThreads = (long long)(E0 + E1) * 16;
    int scatterBlocks = (int)((scatterThreads + 255) / 256);

    for (int l = 0; l < NLAYERS; l++) {
        scatter_both_kernel<<<scatterBlocks, 256>>>(
            rows0, cols0, vals0, ego0, side0, E0,
            rows1, cols1, vals1, ego1, side1, E1);
        layer_both_kernel<<<LBLOCKS0 + LBLOCKS1, 256>>>(
            gcW0, gcb0, biW0, bib0, side0, ego0, alle0,
            gcW1, gcb1, biW1, bib1, side1, ego1, alle1, l);
    }

    // pre-transpose/convert both B operands (fp16 single pass)
    convertB_both_kernel<<<(256 * (KPAD_U + KPAD_I) + 255) / 256, 256>>>(
        alle1, alle1 + (size_t)NU1 * OUTW, bhu, bhi);

    // both residual GEMMs in a single launch (full-N tiles, A read once)
    wmma_gemm_kernel<<<BLOCKS_U + BLOCKS_I, 256, gemm_smem>>>(
        mapu, mapi, bhu, bhi,
        alle0, alle0 + (size_t)NU0 * OUTW,
        out, out + (size_t)NU0 * OUTW);
}

// round 7
// speedup vs baseline: 4.9872x; 1.0164x over previous
#include <cuda_runtime.h>
#include <cuda_fp16.h>
#include <mma.h>
#include <cstdint>

using namespace nvcuda;

// ---------------------------------------------------------------------------
// Problem constants
// ---------------------------------------------------------------------------
#define NU0 20000
#define NI0 15000
#define NU1 4000
#define NI1 3000
#define N0  (NU0 + NI0)   // 35000
#define N1  (NU1 + NI1)   // 7000
#define DEMB 64
#define NLAYERS 3
#define OUTW 256          // D*(L+1)

#define KPAD_U 4032       // multiple of 64
#define KPAD_I 3008       // multiple of 64

#define BLOCKS_U 157      // ceil(20000/128)
#define BLOCKS_I 118      // ceil(15000/128)
#define LBLOCKS0 2188     // ceil(N0/16)
#define LBLOCKS1 438      // ceil(N1/16)

// ---------------------------------------------------------------------------
// Scratch (static device globals)
// ---------------------------------------------------------------------------
__device__ __align__(256) float g_ego0 [N0 * DEMB];
__device__ __align__(256) float g_side0[N0 * DEMB];
__device__ __align__(256) float g_alle0[N0 * OUTW];
__device__ __align__(256) float g_ego1 [N1 * DEMB];
__device__ __align__(256) float g_side1[N1 * DEMB];
__device__ __align__(256) float g_alle1[N1 * OUTW];

// Pre-transposed fp16 B, K-major [256][Kpad], zero-padded.
__device__ __align__(256) __half g_Bh_u[256 * KPAD_U];
__device__ __align__(256) __half g_Bh_i[256 * KPAD_I];

// ---------------------------------------------------------------------------
// init both graphs: ego = concat(ue, ie); alle[:,0:64] = ego; side = 0
// ---------------------------------------------------------------------------
__global__ void init_both_kernel(const float* __restrict__ ue0,
                                 const float* __restrict__ ie0,
                                 const float* __restrict__ ue1,
                                 const float* __restrict__ ie1,
                                 float* __restrict__ ego0,
                                 float* __restrict__ alle0,
                                 float* __restrict__ side0,
                                 float* __restrict__ ego1,
                                 float* __restrict__ alle1,
                                 float* __restrict__ side1) {
    int i = blockIdx.x * blockDim.x + threadIdx.x;
    const float* ue; const float* ie;
    float *ego, *alle, *side;
    int n_users;
    if (i < N0 * DEMB) {
        ue = ue0; ie = ie0; ego = ego0; alle = alle0; side = side0;
        n_users = NU0;
    } else {
        i -= N0 * DEMB;
        if (i >= N1 * DEMB) return;
        ue = ue1; ie = ie1; ego = ego1; alle = alle1; side = side1;
        n_users = NU1;
    }
    int n = i >> 6;
    int d = i & 63;
    float v = (n < n_users) ? ue[n * DEMB + d] : ie[(n - n_users) * DEMB + d];
    ego[i] = v;
    side[i] = 0.f;
    alle[n * OUTW + d] = v;
}

// ---------------------------------------------------------------------------
// merged scatter for both graphs: 16 threads/edge, red.global.add.v4.f32
// ---------------------------------------------------------------------------
__global__ void scatter_both_kernel(
    const int* __restrict__ rows0, const int* __restrict__ cols0,
    const float* __restrict__ vals0, const float* __restrict__ ego0,
    float* __restrict__ side0, int e0,
    const int* __restrict__ rows1, const int* __restrict__ cols1,
    const float* __restrict__ vals1, const float* __restrict__ ego1,
    float* __restrict__ side1, int e1) {

    int t = blockIdx.x * blockDim.x + threadIdx.x;
    int e = t >> 4;
    int c = t & 15;
    const int* rows; const int* cols; const float* vals;
    const float* ego; float* side;
    if (e < e0) {
        rows = rows0; cols = cols0; vals = vals0; ego = ego0; side = side0;
    } else {
        e -= e0;
        if (e >= e1) return;
        rows = rows1; cols = cols1; vals = vals1; ego = ego1; side = side1;
    }
    int   col = cols[e];
    int   row = rows[e];
    float v   = vals[e];
    float4 x = ((const float4*)ego)[col * 16 + c];
    float4 y = make_float4(v * x.x, v * x.y, v * x.z, v * x.w);
    float* dst = side + row * DEMB + c * 4;
    asm volatile("red.global.add.v4.f32 [%0], {%1, %2, %3, %4};"
                 :: "l"(dst), "f"(y.x), "f"(y.y), "f"(y.z), "f"(y.w)
                 : "memory");
}

// ---------------------------------------------------------------------------
// merged layer kernel; also re-zeroes side for the next scatter (layer<2)
// ---------------------------------------------------------------------------
__global__ __launch_bounds__(256) void layer_both_kernel(
    const float* __restrict__ gcW0, const float* __restrict__ gcb0,
    const float* __restrict__ biW0, const float* __restrict__ bib0,
    float* __restrict__ side0g,
    float* __restrict__ ego0g, float* __restrict__ alle0g,
    const float* __restrict__ gcW1, const float* __restrict__ gcb1,
    const float* __restrict__ biW1, const float* __restrict__ bib1,
    float* __restrict__ side1g,
    float* __restrict__ ego1g, float* __restrict__ alle1g,
    int layer) {

    __shared__ float4 sGW[64 * 16];
    __shared__ float4 sBW[64 * 16];
    __shared__ float  sx [16 * 64];
    __shared__ float  sex[16 * 64];

    bool g0 = blockIdx.x < LBLOCKS0;
    const float* gcW  = g0 ? gcW0 : gcW1;
    const float* gcb  = g0 ? gcb0 : gcb1;
    const float* biW  = g0 ? biW0 : biW1;
    const float* bib  = g0 ? bib0 : bib1;
    float* side = g0 ? side0g : side1g;
    float* ego  = g0 ? ego0g : ego1g;
    float* alle = g0 ? alle0g : alle1g;
    int n_nodes = g0 ? N0 : N1;
    int blk     = g0 ? blockIdx.x : blockIdx.x - LBLOCKS0;

    int tid = threadIdx.x;

    const float4* gW4 = (const float4*)(gcW + layer * 64 * 64);
    const float4* bW4 = (const float4*)(biW + layer * 64 * 64);
#pragma unroll
    for (int i = 0; i < 4; i++) {
        sGW[tid + i * 256] = gW4[tid + i * 256];
        sBW[tid + i * 256] = bW4[tid + i * 256];
    }

    int nl = tid >> 4;
    int q  = tid & 15;
    int node = blk * 16 + nl;
    bool valid = node < n_nodes;

    float4 x4 = valid ? ((const float4*)side)[node * 16 + q] : make_float4(0,0,0,0);
    float4 e4 = valid ? ((const float4*)ego )[node * 16 + q] : make_float4(0,0,0,0);

    // re-zero side for the next layer's scatter (one pass saved)
    if (valid && layer < NLAYERS - 1)
        ((float4*)side)[node * 16 + q] = make_float4(0.f, 0.f, 0.f, 0.f);

    sx [nl * 64 + q * 4 + 0] = x4.x;
    sx [nl * 64 + q * 4 + 1] = x4.y;
    sx [nl * 64 + q * 4 + 2] = x4.z;
    sx [nl * 64 + q * 4 + 3] = x4.w;
    sex[nl * 64 + q * 4 + 0] = e4.x * x4.x;
    sex[nl * 64 + q * 4 + 1] = e4.y * x4.y;
    sex[nl * 64 + q * 4 + 2] = e4.z * x4.z;
    sex[nl * 64 + q * 4 + 3] = e4.w * x4.w;
    __syncthreads();

    float4 a = ((const float4*)(gcb + layer * 64))[q];
    float4 b = ((const float4*)(bib + layer * 64))[q];

#pragma unroll
    for (int k = 0; k < 64; k++) {
        float  xk  = sx [nl * 64 + k];
        float  exk = sex[nl * 64 + k];
        float4 wg  = sGW[k * 16 + q];
        float4 wb  = sBW[k * 16 + q];
        a.x += xk * wg.x;  a.y += xk * wg.y;  a.z += xk * wg.z;  a.w += xk * wg.w;
        b.x += exk * wb.x; b.y += exk * wb.y; b.z += exk * wb.z; b.w += exk * wb.w;
    }

    a.x = a.x > 0.f ? a.x : 0.01f * a.x;
    a.y = a.y > 0.f ? a.y : 0.01f * a.y;
    a.z = a.z > 0.f ? a.z : 0.01f * a.z;
    a.w = a.w > 0.f ? a.w : 0.01f * a.w;
    b.x = b.x > 0.f ? b.x : 0.01f * b.x;
    b.y = b.y > 0.f ? b.y : 0.01f * b.y;
    b.z = b.z > 0.f ? b.z : 0.01f * b.z;
    b.w = b.w > 0.f ? b.w : 0.01f * b.w;

    float4 eg;
    eg.x = a.x + b.x; eg.y = a.y + b.y; eg.z = a.z + b.z; eg.w = a.w + b.w;

    float ss = eg.x * eg.x + eg.y * eg.y + eg.z * eg.z + eg.w * eg.w;
#pragma unroll
    for (int off = 8; off > 0; off >>= 1)
        ss += __shfl_xor_sync(0xffffffffu, ss, off);

    float r = 1.0f / fmaxf(sqrtf(ss), 1e-12f);

    if (valid) {
        ((float4*)ego)[node * 16 + q] = eg;
        float4 nrm = make_float4(eg.x * r, eg.y * r, eg.z * r, eg.w * r);
        ((float4*)(alle + node * OUTW + (layer + 1) * 64))[q] = nrm;
    }
}

// ---------------------------------------------------------------------------
// convert both B operands: Bh[n][k] = fp16(B[k][n]) (K-major, zero-padded)
// ---------------------------------------------------------------------------
__global__ void convertB_both_kernel(const float* __restrict__ Bu,
                                     const float* __restrict__ Bi,
                                     __half* __restrict__ hu,
                                     __half* __restrict__ hi) {
    int idx = blockIdx.x * blockDim.x + threadIdx.x;
    const float* B; __half* h; int K, Kpad;
    if (idx < 256 * KPAD_U) {
        B = Bu; h = hu; K = NU1; Kpad = KPAD_U;
    } else {
        idx -= 256 * KPAD_U;
        if (idx >= 256 * KPAD_I) return;
        B = Bi; h = hi; K = NI1; Kpad = KPAD_I;
    }
    int n = idx & 255;
    int k = idx >> 8;
    float v = (k < K) ? B[(size_t)k * 256 + n] : 0.f;
    h[(size_t)n * Kpad + k] = __float2half_rn(v);
}

// ---------------------------------------------------------------------------
// fp16 WMMA GEMM + residual, single pass, cp.async double-buffered, BK=64.
//   out[M,256] = base[M,256] + A[M,K] @ B[K,256]
// CTA tile: 128 rows x 256 cols (A read exactly once).
// 512 threads / 16 warps (4 per SMSP), warp tile 32x64.
// ---------------------------------------------------------------------------
#define LDH 72               // smem leading dim in halves (144B rows)
#define A_TILE (128 * LDH)   // halves per A buffer
#define B_TILE (256 * LDH)   // halves per B buffer

__device__ __forceinline__ void cp_async16(uint32_t saddr, const void* gptr) {
    asm volatile("cp.async.cg.shared.global [%0], [%1], 16;"
                 :: "r"(saddr), "l"(gptr));
}
__device__ __forceinline__ void cp_commit() {
    asm volatile("cp.async.commit_group;");
}
__device__ __forceinline__ void cp_wait_all() {
    asm volatile("cp.async.wait_group 0;" ::: "memory");
}

__global__ __launch_bounds__(512, 1) void wmma_gemm_kernel(
    const float* __restrict__ Au, const float* __restrict__ Ai,
    const __half* __restrict__ Bhu, const __half* __restrict__ Bhi,
    const float* __restrict__ baseU, const float* __restrict__ baseI,
    float* __restrict__ outU, float* __restrict__ outI) {

    extern __shared__ __half sm[];
    __half* As = sm;                  // [2][128][LDH]
    __half* Bs = sm + 2 * A_TILE;     // [2][256][LDH]

    bool isU = blockIdx.x < BLOCKS_U;
    const float*  A    = isU ? Au    : Ai;
    const __half* BHg  = isU ? Bhu   : Bhi;
    const float*  base = isU ? baseU : baseI;
    float*        out  = isU ? outU  : outI;
    int M    = isU ? NU0 : NI0;
    int K    = isU ? NU1 : NI1;
    int Kpad = isU ? KPAD_U : KPAD_I;
    int blockRow = (isU ? blockIdx.x : blockIdx.x - BLOCKS_U) * 128;

    int tid  = threadIdx.x;
    int wid  = tid >> 5;
    int lane = tid & 31;
    int wm = (wid >> 2) * 32;     // 0,32,64,96
    int wn = (wid & 3) * 64;      // 0,64,128,192

    bool interior = (blockRow + 128 <= M);

    uint32_t sBs = (uint32_t)__cvta_generic_to_shared(Bs);

    wmma::fragment<wmma::accumulator, 16, 16, 16, float> c[2][4];
    if (interior) {
#pragma unroll
        for (int i = 0; i < 2; i++)
#pragma unroll
            for (int j = 0; j < 4; j++)
                wmma::load_matrix_sync(
                    c[i][j],
                    base + (size_t)(blockRow + wm + i * 16) * OUTW
                         + wn + j * 16,
                    OUTW, wmma::mem_row_major);
    } else {
#pragma unroll
        for (int i = 0; i < 2; i++)
#pragma unroll
            for (int j = 0; j < 4; j++)
                wmma::fill_fragment(c[i][j], 0.f);
    }

    int nCh = Kpad >> 6;
    float4 aReg[4];

    // prologue: B chunk 0 -> buf 0 (cp.async); A chunk 0 -> regs
    {
#pragma unroll
        for (int i = 0; i < 4; i++) {
            int idx = tid + i * 512;      // 0..2047
            int n = idx >> 3;             // 0..255
            int u = idx & 7;              // 16B unit
            const __half* src = BHg + (size_t)n * Kpad + u * 8;
            cp_async16(sBs + (uint32_t)(n * LDH + u * 8) * 2, src);
        }
        cp_commit();
#pragma unroll
        for (int i = 0; i < 4; i++) {
            int idx = tid + i * 512;      // 0..2047
            int r = idx >> 4;             // 0..127
            int q = idx & 15;             // float4 within 64-col row
            int grow = blockRow + r;
            int gcol = q * 4;
            aReg[i] = (grow < M && gcol < K)
                      ? *(const float4*)(A + (size_t)grow * K + gcol)
                      : make_float4(0.f, 0.f, 0.f, 0.f);
        }
    }

    for (int ch = 0; ch < nCh; ch++) {
        int p = ch & 1;
        __half* Ap = As + p * A_TILE;
        __half* Bp = Bs + p * B_TILE;

        // store prefetched A regs -> smem (fp16 convert)
#pragma unroll
        for (int i = 0; i < 4; i++) {
            int idx = tid + i * 512;
            int r = idx >> 4;
            int q = idx & 15;
            __half2 h01 = __floats2half2_rn(aReg[i].x, aReg[i].y);
            __half2 h23 = __floats2half2_rn(aReg[i].z, aReg[i].w);
            *(__half2*)(Ap + r * LDH + q * 4)     = h01;
            *(__half2*)(Ap + r * LDH + q * 4 + 2) = h23;
        }

        cp_wait_all();     // B(ch) landed
        __syncthreads();   // A stores visible; prior MMA reads complete

        // prefetch next chunk (overlaps with this chunk's MMAs)
        if (ch + 1 < nCh) {
            int kc = (ch + 1) << 6;
            uint32_t sBN = sBs + (uint32_t)((p ^ 1) * B_TILE) * 2;
#pragma unroll
            for (int i = 0; i < 4; i++) {
                int idx = tid + i * 512;
                int n = idx >> 3;
                int u = idx & 7;
                const __half* src = BHg + (size_t)n * Kpad + kc + u * 8;
                cp_async16(sBN + (uint32_t)(n * LDH + u * 8) * 2, src);
            }
            cp_commit();
#pragma unroll
            for (int i = 0; i < 4; i++) {
                int idx = tid + i * 512;
                int r = idx >> 4;
                int q = idx & 15;
                int grow = blockRow + r;
                int gcol = kc + q * 4;
                aReg[i] = (grow < M && gcol < K)
                          ? *(const float4*)(A + (size_t)grow * K + gcol)
                          : make_float4(0.f, 0.f, 0.f, 0.f);
            }
        }

        // MMA: 4 k-frags x (2m x 4n)
#pragma unroll
        for (int kk = 0; kk < 4; kk++) {
            wmma::fragment<wmma::matrix_a, 16, 16, 16, __half, wmma::row_major> af[2];
#pragma unroll
            for (int i = 0; i < 2; i++)
                wmma::load_matrix_sync(af[i], Ap + (wm + i * 16) * LDH + kk * 16, LDH);
#pragma unroll
            for (int j = 0; j < 4; j++) {
                wmma::fragment<wmma::matrix_b, 16, 16, 16, __half, wmma::col_major> bf;
                wmma::load_matrix_sync(bf, Bp + (wn + j * 16) * LDH + kk * 16, LDH);
#pragma unroll
                for (int i = 0; i < 2; i++)
                    wmma::mma_sync(c[i][j], af[i], bf, c[i][j]);
            }
        }
    }

    // ---- epilogue ----
    if (interior) {
#pragma unroll
        for (int i = 0; i < 2; i++)
#pragma unroll
            for (int j = 0; j < 4; j++)
                wmma::store_matrix_sync(
                    out + (size_t)(blockRow + wm + i * 16) * OUTW
                        + wn + j * 16,
                    c[i][j], OUTW, wmma::mem_row_major);
    } else {
        __syncthreads();
        float* stg = (float*)sm + wid * 256;   // per-warp 16x16 staging
#pragma unroll
        for (int i = 0; i < 2; i++)
#pragma unroll
            for (int j = 0; j < 4; j++) {
                wmma::store_matrix_sync(stg, c[i][j], 16, wmma::mem_row_major);
                __syncwarp();
#pragma unroll
                for (int e = 0; e < 8; e++) {
                    int el = lane + e * 32;
                    int r  = el >> 4;
                    int cc = el & 15;
                    int grow = blockRow + wm + i * 16 + r;
                    if (grow < M) {
                        int gc = wn + j * 16 + cc;
                        out[(size_t)grow * OUTW + gc] =
                            stg[el] + base[(size_t)grow * OUTW + gc];
                    }
                }
                __syncwarp();
            }
    }
}

// ---------------------------------------------------------------------------
// Launch
// ---------------------------------------------------------------------------
extern "C" void kernel_launch(void* const* d_in, const int* in_sizes, int n_in,
                              void* d_out, int out_size) {
    const float* ue0  = (const float*)d_in[0];
    const float* ie0  = (const float*)d_in[1];
    const float* gcW0 = (const float*)d_in[2];
    const float* gcb0 = (const float*)d_in[3];
    const float* biW0 = (const float*)d_in[4];
    const float* bib0 = (const float*)d_in[5];
    const float* ue1  = (const float*)d_in[6];
    const float* ie1  = (const float*)d_in[7];
    const float* gcW1 = (const float*)d_in[8];
    const float* gcb1 = (const float*)d_in[9];
    const float* biW1 = (const float*)d_in[10];
    const float* bib1 = (const float*)d_in[11];
    const float* mapu = (const float*)d_in[12];
    const float* mapi = (const float*)d_in[13];
    const float* vals0 = (const float*)d_in[14];
    const float* vals1 = (const float*)d_in[15];
    const int*   rows0 = (const int*)d_in[16];
    const int*   cols0 = (const int*)d_in[17];
    const int*   rows1 = (const int*)d_in[18];
    const int*   cols1 = (const int*)d_in[19];
    float* out = (float*)d_out;

    int E0 = in_sizes[14];
    int E1 = in_sizes[15];

    float *ego0, *side0, *alle0, *ego1, *side1, *alle1;
    cudaGetSymbolAddress((void**)&ego0,  g_ego0);
    cudaGetSymbolAddress((void**)&side0, g_side0);
    cudaGetSymbolAddress((void**)&alle0, g_alle0);
    cudaGetSymbolAddress((void**)&ego1,  g_ego1);
    cudaGetSymbolAddress((void**)&side1, g_side1);
    cudaGetSymbolAddress((void**)&alle1, g_alle1);

    __half *bhu, *bhi;
    cudaGetSymbolAddress((void**)&bhu, g_Bh_u);
    cudaGetSymbolAddress((void**)&bhi, g_Bh_i);

    const int gemm_smem = (2 * A_TILE + 2 * B_TILE) * sizeof(__half); // 110592
    cudaFuncSetAttribute(wmma_gemm_kernel,
                         cudaFuncAttributeMaxDynamicSharedMemorySize,
                         gemm_smem);

    // init (both graphs, also zeroes side)
    init_both_kernel<<<((N0 + N1) * DEMB + 255) / 256, 256>>>(
        ue0, ie0, ue1, ie1, ego0, alle0, side0, ego1, alle1, side1);

    long long scatterThreads = (long long)(E0 + E1) * 16;
    int scatterBlocks = (int)((scatterThreads + 255) / 256);

    for (int l = 0; l < NLAYERS; l++) {
        scatter_both_kernel<<<scatterBlocks, 256>>>(
            rows0, cols0, vals0, ego0, side0, E0,
            rows1, cols1, vals1, ego1, side1, E1);
        layer_both_kernel<<<LBLOCKS0 + LBLOCKS1, 256>>>(
            gcW0, gcb0, biW0, bib0, side0, ego0, alle0,
            gcW1, gcb1, biW1, bib1, side1, ego1, alle1, l);
    }

    // pre-transpose/convert both B operands (fp16 single pass)
    convertB_both_kernel<<<(256 * (KPAD_U + KPAD_I) + 255) / 256, 256>>>(
        alle1, alle1 + (size_t)NU1 * OUTW, bhu, bhi);

    // both residual GEMMs in a single launch (full-N tiles, A read once)
    wmma_gemm_kernel<<<BLOCKS_U + BLOCKS_I, 512, gemm_smem>>>(
        mapu, mapi, bhu, bhi,
        alle0, alle0 + (size_t)NU0 * OUTW,
        out, out + (size_t)NU0 * OUTW);
}

// round 8
// speedup vs baseline: 5.0600x; 1.0146x over previous
#include <cuda_runtime.h>
#include <cuda_fp16.h>
#include <mma.h>
#include <cstdint>

using namespace nvcuda;

// ---------------------------------------------------------------------------
// Problem constants
// ---------------------------------------------------------------------------
#define NU0 20000
#define NI0 15000
#define NU1 4000
#define NI1 3000
#define N0  (NU0 + NI0)   // 35000
#define N1  (NU1 + NI1)   // 7000
#define DEMB 64
#define NLAYERS 3
#define OUTW 256          // D*(L+1)

#define KPAD_U 4032       // multiple of 64
#define KPAD_I 3008       // multiple of 64

#define BLOCKS_U 313      // ceil(20000/64)
#define BLOCKS_I 235      // ceil(15000/64)
#define LBLOCKS0 2188     // ceil(N0/16)
#define LBLOCKS1 438      // ceil(N1/16)

// ---------------------------------------------------------------------------
// Scratch (static device globals)
// ---------------------------------------------------------------------------
__device__ __align__(256) float g_ego0 [N0 * DEMB];
__device__ __align__(256) float g_side0[N0 * DEMB];
__device__ __align__(256) float g_alle0[N0 * OUTW];
__device__ __align__(256) float g_ego1 [N1 * DEMB];
__device__ __align__(256) float g_side1[N1 * DEMB];
__device__ __align__(256) float g_alle1[N1 * OUTW];

// Pre-transposed fp16 B, K-major [256][Kpad], zero-padded.
__device__ __align__(256) __half g_Bh_u[256 * KPAD_U];
__device__ __align__(256) __half g_Bh_i[256 * KPAD_I];

// ---------------------------------------------------------------------------
// init both graphs: ego = concat(ue, ie); alle[:,0:64] = ego; side = 0
// ---------------------------------------------------------------------------
__global__ void init_both_kernel(const float* __restrict__ ue0,
                                 const float* __restrict__ ie0,
                                 const float* __restrict__ ue1,
                                 const float* __restrict__ ie1,
                                 float* __restrict__ ego0,
                                 float* __restrict__ alle0,
                                 float* __restrict__ side0,
                                 float* __restrict__ ego1,
                                 float* __restrict__ alle1,
                                 float* __restrict__ side1) {
    int i = blockIdx.x * blockDim.x + threadIdx.x;
    const float* ue; const float* ie;
    float *ego, *alle, *side;
    int n_users;
    if (i < N0 * DEMB) {
        ue = ue0; ie = ie0; ego = ego0; alle = alle0; side = side0;
        n_users = NU0;
    } else {
        i -= N0 * DEMB;
        if (i >= N1 * DEMB) return;
        ue = ue1; ie = ie1; ego = ego1; alle = alle1; side = side1;
        n_users = NU1;
    }
    int n = i >> 6;
    int d = i & 63;
    float v = (n < n_users) ? ue[n * DEMB + d] : ie[(n - n_users) * DEMB + d];
    ego[i] = v;
    side[i] = 0.f;
    alle[n * OUTW + d] = v;
}

// ---------------------------------------------------------------------------
// merged scatter for both graphs: 16 threads/edge, red.global.add.v4.f32
// ---------------------------------------------------------------------------
__global__ void scatter_both_kernel(
    const int* __restrict__ rows0, const int* __restrict__ cols0,
    const float* __restrict__ vals0, const float* __restrict__ ego0,
    float* __restrict__ side0, int e0,
    const int* __restrict__ rows1, const int* __restrict__ cols1,
    const float* __restrict__ vals1, const float* __restrict__ ego1,
    float* __restrict__ side1, int e1) {

    int t = blockIdx.x * blockDim.x + threadIdx.x;
    int e = t >> 4;
    int c = t & 15;
    const int* rows; const int* cols; const float* vals;
    const float* ego; float* side;
    if (e < e0) {
        rows = rows0; cols = cols0; vals = vals0; ego = ego0; side = side0;
    } else {
        e -= e0;
        if (e >= e1) return;
        rows = rows1; cols = cols1; vals = vals1; ego = ego1; side = side1;
    }
    int   col = cols[e];
    int   row = rows[e];
    float v   = vals[e];
    float4 x = ((const float4*)ego)[col * 16 + c];
    float4 y = make_float4(v * x.x, v * x.y, v * x.z, v * x.w);
    float* dst = side + row * DEMB + c * 4;
    asm volatile("red.global.add.v4.f32 [%0], {%1, %2, %3, %4};"
                 :: "l"(dst), "f"(y.x), "f"(y.y), "f"(y.z), "f"(y.w)
                 : "memory");
}

// ---------------------------------------------------------------------------
// merged layer kernel; also re-zeroes side for the next scatter (layer<2)
// ---------------------------------------------------------------------------
__global__ __launch_bounds__(256) void layer_both_kernel(
    const float* __restrict__ gcW0, const float* __restrict__ gcb0,
    const float* __restrict__ biW0, const float* __restrict__ bib0,
    float* __restrict__ side0g,
    float* __restrict__ ego0g, float* __restrict__ alle0g,
    const float* __restrict__ gcW1, const float* __restrict__ gcb1,
    const float* __restrict__ biW1, const float* __restrict__ bib1,
    float* __restrict__ side1g,
    float* __restrict__ ego1g, float* __restrict__ alle1g,
    int layer) {

    __shared__ float4 sGW[64 * 16];
    __shared__ float4 sBW[64 * 16];
    __shared__ float  sx [16 * 64];
    __shared__ float  sex[16 * 64];

    bool g0 = blockIdx.x < LBLOCKS0;
    const float* gcW  = g0 ? gcW0 : gcW1;
    const float* gcb  = g0 ? gcb0 : gcb1;
    const float* biW  = g0 ? biW0 : biW1;
    const float* bib  = g0 ? bib0 : bib1;
    float* side = g0 ? side0g : side1g;
    float* ego  = g0 ? ego0g : ego1g;
    float* alle = g0 ? alle0g : alle1g;
    int n_nodes = g0 ? N0 : N1;
    int blk     = g0 ? blockIdx.x : blockIdx.x - LBLOCKS0;

    int tid = threadIdx.x;

    const float4* gW4 = (const float4*)(gcW + layer * 64 * 64);
    const float4* bW4 = (const float4*)(biW + layer * 64 * 64);
#pragma unroll
    for (int i = 0; i < 4; i++) {
        sGW[tid + i * 256] = gW4[tid + i * 256];
        sBW[tid + i * 256] = bW4[tid + i * 256];
    }

    int nl = tid >> 4;
    int q  = tid & 15;
    int node = blk * 16 + nl;
    bool valid = node < n_nodes;

    float4 x4 = valid ? ((const float4*)side)[node * 16 + q] : make_float4(0,0,0,0);
    float4 e4 = valid ? ((const float4*)ego )[node * 16 + q] : make_float4(0,0,0,0);

    // re-zero side for the next layer's scatter (one pass saved)
    if (valid && layer < NLAYERS - 1)
        ((float4*)side)[node * 16 + q] = make_float4(0.f, 0.f, 0.f, 0.f);

    sx [nl * 64 + q * 4 + 0] = x4.x;
    sx [nl * 64 + q * 4 + 1] = x4.y;
    sx [nl * 64 + q * 4 + 2] = x4.z;
    sx [nl * 64 + q * 4 + 3] = x4.w;
    sex[nl * 64 + q * 4 + 0] = e4.x * x4.x;
    sex[nl * 64 + q * 4 + 1] = e4.y * x4.y;
    sex[nl * 64 + q * 4 + 2] = e4.z * x4.z;
    sex[nl * 64 + q * 4 + 3] = e4.w * x4.w;
    __syncthreads();

    float4 a = ((const float4*)(gcb + layer * 64))[q];
    float4 b = ((const float4*)(bib + layer * 64))[q];

#pragma unroll
    for (int k = 0; k < 64; k++) {
        float  xk  = sx [nl * 64 + k];
        float  exk = sex[nl * 64 + k];
        float4 wg  = sGW[k * 16 + q];
        float4 wb  = sBW[k * 16 + q];
        a.x += xk * wg.x;  a.y += xk * wg.y;  a.z += xk * wg.z;  a.w += xk * wg.w;
        b.x += exk * wb.x; b.y += exk * wb.y; b.z += exk * wb.z; b.w += exk * wb.w;
    }

    a.x = a.x > 0.f ? a.x : 0.01f * a.x;
    a.y = a.y > 0.f ? a.y : 0.01f * a.y;
    a.z = a.z > 0.f ? a.z : 0.01f * a.z;
    a.w = a.w > 0.f ? a.w : 0.01f * a.w;
    b.x = b.x > 0.f ? b.x : 0.01f * b.x;
    b.y = b.y > 0.f ? b.y : 0.01f * b.y;
    b.z = b.z > 0.f ? b.z : 0.01f * b.z;
    b.w = b.w > 0.f ? b.w : 0.01f * b.w;

    float4 eg;
    eg.x = a.x + b.x; eg.y = a.y + b.y; eg.z = a.z + b.z; eg.w = a.w + b.w;

    float ss = eg.x * eg.x + eg.y * eg.y + eg.z * eg.z + eg.w * eg.w;
#pragma unroll
    for (int off = 8; off > 0; off >>= 1)
        ss += __shfl_xor_sync(0xffffffffu, ss, off);

    float r = 1.0f / fmaxf(sqrtf(ss), 1e-12f);

    if (valid) {
        ((float4*)ego)[node * 16 + q] = eg;
        float4 nrm = make_float4(eg.x * r, eg.y * r, eg.z * r, eg.w * r);
        ((float4*)(alle + node * OUTW + (layer + 1) * 64))[q] = nrm;
    }
}

// ---------------------------------------------------------------------------
// convert both B operands: Bh[n][k] = fp16(B[k][n]) (K-major, zero-padded)
// ---------------------------------------------------------------------------
__global__ void convertB_both_kernel(const float* __restrict__ Bu,
                                     const float* __restrict__ Bi,
                                     __half* __restrict__ hu,
                                     __half* __restrict__ hi) {
    int idx = blockIdx.x * blockDim.x + threadIdx.x;
    const float* B; __half* h; int K, Kpad;
    if (idx < 256 * KPAD_U) {
        B = Bu; h = hu; K = NU1; Kpad = KPAD_U;
    } else {
        idx -= 256 * KPAD_U;
        if (idx >= 256 * KPAD_I) return;
        B = Bi; h = hi; K = NI1; Kpad = KPAD_I;
    }
    int n = idx & 255;
    int k = idx >> 8;
    float v = (k < K) ? B[(size_t)k * 256 + n] : 0.f;
    h[(size_t)n * Kpad + k] = __float2half_rn(v);
}

// ---------------------------------------------------------------------------
// fp16 WMMA GEMM + residual, single pass, cp.async double-buffered, BK=64.
//   out[M,256] = base[M,256] + A[M,K] @ B[K,256]
// CTA tile: 64 rows x 256 cols (A read once). 256 thr / 8 warps, warp 32x64.
// 92 KB smem -> 2 CTAs per SM (cross-CTA latency hiding).
// ---------------------------------------------------------------------------
#define LDH 72               // smem leading dim in halves (144B rows)
#define A_TILE (64 * LDH)    // halves per A buffer
#define B_TILE (256 * LDH)   // halves per B buffer

__device__ __forceinline__ void cp_async16(uint32_t saddr, const void* gptr) {
    asm volatile("cp.async.cg.shared.global [%0], [%1], 16;"
                 :: "r"(saddr), "l"(gptr));
}
__device__ __forceinline__ void cp_commit() {
    asm volatile("cp.async.commit_group;");
}
__device__ __forceinline__ void cp_wait_all() {
    asm volatile("cp.async.wait_group 0;" ::: "memory");
}

__global__ __launch_bounds__(256, 2) void wmma_gemm_kernel(
    const float* __restrict__ Au, const float* __restrict__ Ai,
    const __half* __restrict__ Bhu, const __half* __restrict__ Bhi,
    const float* __restrict__ baseU, const float* __restrict__ baseI,
    float* __restrict__ outU, float* __restrict__ outI) {

    extern __shared__ __half sm[];
    __half* As = sm;                  // [2][64][LDH]
    __half* Bs = sm + 2 * A_TILE;     // [2][256][LDH]

    bool isU = blockIdx.x < BLOCKS_U;
    const float*  A    = isU ? Au    : Ai;
    const __half* BHg  = isU ? Bhu   : Bhi;
    const float*  base = isU ? baseU : baseI;
    float*        out  = isU ? outU  : outI;
    int M    = isU ? NU0 : NI0;
    int K    = isU ? NU1 : NI1;
    int Kpad = isU ? KPAD_U : KPAD_I;
    int blockRow = (isU ? blockIdx.x : blockIdx.x - BLOCKS_U) * 64;

    int tid  = threadIdx.x;
    int wid  = tid >> 5;
    int lane = tid & 31;
    int wm = (wid >> 2) * 32;     // 0 or 32
    int wn = (wid & 3) * 64;      // 0,64,128,192

    bool interior = (blockRow + 64 <= M);

    // A-load mapping: 4 float4 per thread per chunk (64 rows x 64 cols)
    int ar = tid >> 4;            // 0..15 (rows +i*16)
    int aq = tid & 15;            // float4 index within 64-col row
    // B-load mapping: 8 x 16B units per chunk (256 rows x 128B)
    int bn = tid >> 3;            // 0..31 (rows +i*32)
    int bu = tid & 7;             // 16B unit within row

    uint32_t sBs = (uint32_t)__cvta_generic_to_shared(Bs);

    wmma::fragment<wmma::accumulator, 16, 16, 16, float> c[2][4];
    if (interior) {
#pragma unroll
        for (int i = 0; i < 2; i++)
#pragma unroll
            for (int j = 0; j < 4; j++)
                wmma::load_matrix_sync(
                    c[i][j],
                    base + (size_t)(blockRow + wm + i * 16) * OUTW
                         + wn + j * 16,
                    OUTW, wmma::mem_row_major);
    } else {
#pragma unroll
        for (int i = 0; i < 2; i++)
#pragma unroll
            for (int j = 0; j < 4; j++)
                wmma::fill_fragment(c[i][j], 0.f);
    }

    int nCh = Kpad >> 6;
    float4 aReg[4];

    // prologue: B chunk 0 -> buf 0 (cp.async); A chunk 0 -> regs
    {
#pragma unroll
        for (int i = 0; i < 8; i++) {
            int n = bn + i * 32;
            const __half* src = BHg + (size_t)n * Kpad + bu * 8;
            cp_async16(sBs + (uint32_t)(n * LDH + bu * 8) * 2, src);
        }
        cp_commit();
#pragma unroll
        for (int i = 0; i < 4; i++) {
            int r = ar + i * 16;
            int grow = blockRow + r;
            int gcol = aq * 4;
            aReg[i] = (grow < M && gcol < K)
                      ? *(const float4*)(A + (size_t)grow * K + gcol)
                      : make_float4(0.f, 0.f, 0.f, 0.f);
        }
    }

    for (int ch = 0; ch < nCh; ch++) {
        int p = ch & 1;
        __half* Ap = As + p * A_TILE;
        __half* Bp = Bs + p * B_TILE;

        // store prefetched A regs -> smem (fp16 convert)
#pragma unroll
        for (int i = 0; i < 4; i++) {
            int r = ar + i * 16;
            __half2 h01 = __floats2half2_rn(aReg[i].x, aReg[i].y);
            __half2 h23 = __floats2half2_rn(aReg[i].z, aReg[i].w);
            *(__half2*)(Ap + r * LDH + aq * 4)     = h01;
            *(__half2*)(Ap + r * LDH + aq * 4 + 2) = h23;
        }

        cp_wait_all();     // B(ch) landed
        __syncthreads();   // A stores visible; prior MMA reads complete

        // prefetch next chunk (overlaps with this chunk's MMAs)
        if (ch + 1 < nCh) {
            int kc = (ch + 1) << 6;
            uint32_t sBN = sBs + (uint32_t)((p ^ 1) * B_TILE) * 2;
#pragma unroll
            for (int i = 0; i < 8; i++) {
                int n = bn + i * 32;
                const __half* src = BHg + (size_t)n * Kpad + kc + bu * 8;
                cp_async16(sBN + (uint32_t)(n * LDH + bu * 8) * 2, src);
            }
            cp_commit();
#pragma unroll
            for (int i = 0; i < 4; i++) {
                int r = ar + i * 16;
                int grow = blockRow + r;
                int gcol = kc + aq * 4;
                aReg[i] = (grow < M && gcol < K)
                          ? *(const float4*)(A + (size_t)grow * K + gcol)
                          : make_float4(0.f, 0.f, 0.f, 0.f);
            }
        }

        // MMA: 4 k-frags x (2m x 4n)
#pragma unroll
        for (int kk = 0; kk < 4; kk++) {
            wmma::fragment<wmma::matrix_a, 16, 16, 16, __half, wmma::row_major> af[2];
#pragma unroll
            for (int i = 0; i < 2; i++)
                wmma::load_matrix_sync(af[i], Ap + (wm + i * 16) * LDH + kk * 16, LDH);
#pragma unroll
            for (int j = 0; j < 4; j++) {
                wmma::fragment<wmma::matrix_b, 16, 16, 16, __half, wmma::col_major> bf;
                wmma::load_matrix_sync(bf, Bp + (wn + j * 16) * LDH + kk * 16, LDH);
#pragma unroll
                for (int i = 0; i < 2; i++)
                    wmma::mma_sync(c[i][j], af[i], bf, c[i][j]);
            }
        }
    }

    // ---- epilogue ----
    if (interior) {
#pragma unroll
        for (int i = 0; i < 2; i++)
#pragma unroll
            for (int j = 0; j < 4; j++)
                wmma::store_matrix_sync(
                    out + (size_t)(blockRow + wm + i * 16) * OUTW
                        + wn + j * 16,
                    c[i][j], OUTW, wmma::mem_row_major);
    } else {
        __syncthreads();
        float* stg = (float*)sm + wid * 256;   // per-warp 16x16 staging
#pragma unroll
        for (int i = 0; i < 2; i++)
#pragma unroll
            for (int j = 0; j < 4; j++) {
                wmma::store_matrix_sync(stg, c[i][j], 16, wmma::mem_row_major);
                __syncwarp();
#pragma unroll
                for (int e = 0; e < 8; e++) {
                    int el = lane + e * 32;
                    int r  = el >> 4;
                    int cc = el & 15;
                    int grow = blockRow + wm + i * 16 + r;
                    if (grow < M) {
                        int gc = wn + j * 16 + cc;
                        out[(size_t)grow * OUTW + gc] =
                            stg[el] + base[(size_t)grow * OUTW + gc];
                    }
                }
                __syncwarp();
            }
    }
}

// ---------------------------------------------------------------------------
// Launch
// ---------------------------------------------------------------------------
extern "C" void kernel_launch(void* const* d_in, const int* in_sizes, int n_in,
                              void* d_out, int out_size) {
    const float* ue0  = (const float*)d_in[0];
    const float* ie0  = (const float*)d_in[1];
    const float* gcW0 = (const float*)d_in[2];
    const float* gcb0 = (const float*)d_in[3];
    const float* biW0 = (const float*)d_in[4];
    const float* bib0 = (const float*)d_in[5];
    const float* ue1  = (const float*)d_in[6];
    const float* ie1  = (const float*)d_in[7];
    const float* gcW1 = (const float*)d_in[8];
    const float* gcb1 = (const float*)d_in[9];
    const float* biW1 = (const float*)d_in[10];
    const float* bib1 = (const float*)d_in[11];
    const float* mapu = (const float*)d_in[12];
    const float* mapi = (const float*)d_in[13];
    const float* vals0 = (const float*)d_in[14];
    const float* vals1 = (const float*)d_in[15];
    const int*   rows0 = (const int*)d_in[16];
    const int*   cols0 = (const int*)d_in[17];
    const int*   rows1 = (const int*)d_in[18];
    const int*   cols1 = (const int*)d_in[19];
    float* out = (float*)d_out;

    int E0 = in_sizes[14];
    int E1 = in_sizes[15];

    float *ego0, *side0, *alle0, *ego1, *side1, *alle1;
    cudaGetSymbolAddress((void**)&ego0,  g_ego0);
    cudaGetSymbolAddress((void**)&side0, g_side0);
    cudaGetSymbolAddress((void**)&alle0, g_alle0);
    cudaGetSymbolAddress((void**)&ego1,  g_ego1);
    cudaGetSymbolAddress((void**)&side1, g_side1);
    cudaGetSymbolAddress((void**)&alle1, g_alle1);

    __half *bhu, *bhi;
    cudaGetSymbolAddress((void**)&bhu, g_Bh_u);
    cudaGetSymbolAddress((void**)&bhi, g_Bh_i);

    const int gemm_smem = (2 * A_TILE + 2 * B_TILE) * sizeof(__half); // 92160
    cudaFuncSetAttribute(wmma_gemm_kernel,
                         cudaFuncAttributeMaxDynamicSharedMemorySize,
                         gemm_smem);

    // init (both graphs, also zeroes side)
    init_both_kernel<<<((N0 + N1) * DEMB + 255) / 256, 256>>>(
        ue0, ie0, ue1, ie1, ego0, alle0, side0, ego1, alle1, side1);

    long long scatterThreads = (long long)(E0 + E1) * 16;
    int scatterBlocks = (int)((scatterThreads + 255) / 256);

    for (int l = 0; l < NLAYERS; l++) {
        scatter_both_kernel<<<scatterBlocks, 256>>>(
            rows0, cols0, vals0, ego0, side0, E0,
            rows1, cols1, vals1, ego1, side1, E1);
        layer_both_kernel<<<LBLOCKS0 + LBLOCKS1, 256>>>(
            gcW0, gcb0, biW0, bib0, side0, ego0, alle0,
            gcW1, gcb1, biW1, bib1, side1, ego1, alle1, l);
    }

    // pre-transpose/convert both B operands (fp16 single pass)
    convertB_both_kernel<<<(256 * (KPAD_U + KPAD_I) + 255) / 256, 256>>>(
        alle1, alle1 + (size_t)NU1 * OUTW, bhu, bhi);

    // both residual GEMMs in a single launch (64x256 tiles, 2 CTAs/SM)
    wmma_gemm_kernel<<<BLOCKS_U + BLOCKS_I, 256, gemm_smem>>>(
        mapu, mapi, bhu, bhi,
        alle0, alle0 + (size_t)NU0 * OUTW,
        out, out + (size_t)NU0 * OUTW);
}